// round 1
// baseline (speedup 1.0000x reference)
#include <cuda_runtime.h>

#define NN 5000
#define IN_DIM 64
#define HID 32
#define NH 4
#define F1 (NH*HID)   // 128
#define OUTD 64
#define CAP 320       // max degree cap (Binomial(5000,0.02) max ~140; 320 is safe)
#define NEG_SLOPE 0.2f

// ---------------- device scratch (no allocations allowed) ----------------
__device__ int   g_deg[NN];
__device__ int   g_nbr[NN * CAP];
__device__ float g_Wh1[NN * F1];
__device__ float g_s1src[NN * NH];
__device__ float g_s1dst[NN * NH];
__device__ float g_x[NN * F1];
__device__ float g_Wh2[NN * OUTD];
__device__ float g_s2src[NN];
__device__ float g_s2dst[NN];

// ---------------- 1) build neighbor lists (deterministic, one warp/row) ---
__global__ void build_nbr(const float* __restrict__ adj) {
    const int wpb = blockDim.x >> 5;
    const int row = blockIdx.x * wpb + (threadIdx.x >> 5);
    if (row >= NN) return;
    const int lane = threadIdx.x & 31;
    const float* __restrict__ r = adj + (size_t)row * NN;
    int base = 0;
    // 39 full iterations of 128 cols via float4 (4992 cols), then 8-col tail
    for (int c0 = 0; c0 < 4992; c0 += 128) {
        float4 v = *reinterpret_cast<const float4*>(r + c0 + lane * 4);
        int m = (v.x > 0.f) | ((v.y > 0.f) << 1) | ((v.z > 0.f) << 2) | ((v.w > 0.f) << 3);
        int cnt = __popc(m);
        int pref = cnt;
        #pragma unroll
        for (int d = 1; d < 32; d <<= 1) {
            int t = __shfl_up_sync(0xffffffffu, pref, d);
            if (lane >= d) pref += t;
        }
        int total = __shfl_sync(0xffffffffu, pref, 31);
        int o = base + (pref - cnt);
        int col = c0 + lane * 4;
        if (m & 1) { if (o < CAP) g_nbr[row * CAP + o] = col;     o++; }
        if (m & 2) { if (o < CAP) g_nbr[row * CAP + o] = col + 1; o++; }
        if (m & 4) { if (o < CAP) g_nbr[row * CAP + o] = col + 2; o++; }
        if (m & 8) { if (o < CAP) g_nbr[row * CAP + o] = col + 3; o++; }
        base += total;
    }
    {
        int c = 4992 + lane;
        int pred = (lane < 8) && (r[c] > 0.f);
        unsigned mk = __ballot_sync(0xffffffffu, pred);
        int pos = __popc(mk & ((1u << lane) - 1u));
        if (pred && base + pos < CAP) g_nbr[row * CAP + base + pos] = c;
        base += __popc(mk);
    }
    if (lane == 0) g_deg[row] = base < CAP ? base : CAP;
}

// ---------------- 2) Wh1 = h @ W1, fused s1_src/s1_dst ----------------
__global__ void gemm1(const float* __restrict__ h, const float* __restrict__ W1,
                      const float* __restrict__ a1s, const float* __restrict__ a1d) {
    const int n = blockIdx.x;
    const int k = threadIdx.x;   // 0..127
    __shared__ float sh[IN_DIM];
    if (k < IN_DIM) sh[k] = h[n * IN_DIM + k];
    __syncthreads();
    float acc = 0.f;
    #pragma unroll
    for (int i = 0; i < IN_DIM; i++) acc = fmaf(sh[i], W1[i * F1 + k], acc);
    g_Wh1[n * F1 + k] = acc;
    const int hh = k >> 5, f = k & 31;
    float ps = acc * a1s[hh * HID + f];
    float pd = acc * a1d[hh * HID + f];
    #pragma unroll
    for (int d = 16; d; d >>= 1) {
        ps += __shfl_xor_sync(0xffffffffu, ps, d);
        pd += __shfl_xor_sync(0xffffffffu, pd, d);
    }
    if (f == 0) { g_s1src[n * NH + hh] = ps; g_s1dst[n * NH + hh] = pd; }
}

// ---------------- 3) layer-1 sparse softmax-aggregate + ELU ----------------
__global__ void agg1() {
    const int i = blockIdx.x;
    const int tid = threadIdx.x;     // 128
    __shared__ int   snbr[CAP];
    __shared__ float sw[NH * CAP];
    __shared__ int   sdeg;
    if (tid == 0) sdeg = g_deg[i];
    __syncthreads();
    const int deg = sdeg;
    for (int t = tid; t < deg; t += 128) snbr[t] = g_nbr[i * CAP + t];
    __syncthreads();
    // raw leaky scores
    for (int t = tid; t < deg * NH; t += 128) {
        int hh = t / deg, j = t - hh * deg;
        float e = g_s1src[i * NH + hh] + g_s1dst[snbr[j] * NH + hh];
        sw[hh * CAP + j] = e > 0.f ? e : NEG_SLOPE * e;
    }
    __syncthreads();
    const int hh = tid >> 5, lane = tid & 31;
    // warp hh owns head hh: max, sumexp, normalize in place
    float m = -1e30f;
    for (int j = lane; j < deg; j += 32) m = fmaxf(m, sw[hh * CAP + j]);
    #pragma unroll
    for (int d = 16; d; d >>= 1) m = fmaxf(m, __shfl_xor_sync(0xffffffffu, m, d));
    float s = 0.f;
    for (int j = lane; j < deg; j += 32) s += __expf(sw[hh * CAP + j] - m);
    #pragma unroll
    for (int d = 16; d; d >>= 1) s += __shfl_xor_sync(0xffffffffu, s, d);
    const float rinv = 1.f / s;
    for (int j = lane; j < deg; j += 32) sw[hh * CAP + j] = __expf(sw[hh * CAP + j] - m) * rinv;
    __syncthreads();
    // gather-accumulate: Wh1 is L2-resident (2.5 MB)
    float acc = 0.f;
    const float* __restrict__ wr = sw + hh * CAP;
    int j = 0;
    #pragma unroll 4
    for (; j + 4 <= deg; j += 4) {
        int n0 = snbr[j], n1 = snbr[j+1], n2 = snbr[j+2], n3 = snbr[j+3];
        float v0 = g_Wh1[n0 * F1 + tid];
        float v1 = g_Wh1[n1 * F1 + tid];
        float v2 = g_Wh1[n2 * F1 + tid];
        float v3 = g_Wh1[n3 * F1 + tid];
        acc = fmaf(wr[j],   v0, acc);
        acc = fmaf(wr[j+1], v1, acc);
        acc = fmaf(wr[j+2], v2, acc);
        acc = fmaf(wr[j+3], v3, acc);
    }
    for (; j < deg; j++) acc = fmaf(wr[j], g_Wh1[snbr[j] * F1 + tid], acc);
    // ELU epilogue
    g_x[i * F1 + tid] = acc > 0.f ? acc : (__expf(acc) - 1.f);
}

// ---------------- 4) Wh2 = x @ W2, fused s2_src/s2_dst ----------------
__global__ void gemm2(const float* __restrict__ W2,
                      const float* __restrict__ a2s, const float* __restrict__ a2d) {
    const int n = blockIdx.x;
    const int k = threadIdx.x;   // 0..63
    __shared__ float sh[F1];
    sh[k] = g_x[n * F1 + k];
    sh[k + 64] = g_x[n * F1 + k + 64];
    __syncthreads();
    float acc = 0.f;
    #pragma unroll
    for (int i = 0; i < F1; i++) acc = fmaf(sh[i], W2[i * OUTD + k], acc);
    g_Wh2[n * OUTD + k] = acc;
    float ps = acc * a2s[k];
    float pd = acc * a2d[k];
    #pragma unroll
    for (int d = 16; d; d >>= 1) {
        ps += __shfl_xor_sync(0xffffffffu, ps, d);
        pd += __shfl_xor_sync(0xffffffffu, pd, d);
    }
    __shared__ float r[4];
    if ((k & 31) == 0) { r[(k >> 5) * 2] = ps; r[(k >> 5) * 2 + 1] = pd; }
    __syncthreads();
    if (k == 0) { g_s2src[n] = r[0] + r[2]; g_s2dst[n] = r[1] + r[3]; }
}

// ---------------- 5) layer-2 sparse softmax-aggregate -> out ----------------
__global__ void agg2(float* __restrict__ out) {
    const int i = blockIdx.x;
    const int tid = threadIdx.x;     // 64
    __shared__ int   snbr[CAP];
    __shared__ float sw[CAP];
    __shared__ int   sdeg;
    if (tid == 0) sdeg = g_deg[i];
    __syncthreads();
    const int deg = sdeg;
    for (int t = tid; t < deg; t += 64) snbr[t] = g_nbr[i * CAP + t];
    __syncthreads();
    const float ssrc = g_s2src[i];
    for (int t = tid; t < deg; t += 64) {
        float e = ssrc + g_s2dst[snbr[t]];
        sw[t] = e > 0.f ? e : NEG_SLOPE * e;
    }
    __syncthreads();
    if (tid < 32) {
        float m = -1e30f;
        for (int j = tid; j < deg; j += 32) m = fmaxf(m, sw[j]);
        #pragma unroll
        for (int d = 16; d; d >>= 1) m = fmaxf(m, __shfl_xor_sync(0xffffffffu, m, d));
        float s = 0.f;
        for (int j = tid; j < deg; j += 32) s += __expf(sw[j] - m);
        #pragma unroll
        for (int d = 16; d; d >>= 1) s += __shfl_xor_sync(0xffffffffu, s, d);
        const float rinv = 1.f / s;
        for (int j = tid; j < deg; j += 32) sw[j] = __expf(sw[j] - m) * rinv;
    }
    __syncthreads();
    float acc = 0.f;
    int j = 0;
    #pragma unroll 4
    for (; j + 4 <= deg; j += 4) {
        int n0 = snbr[j], n1 = snbr[j+1], n2 = snbr[j+2], n3 = snbr[j+3];
        float v0 = g_Wh2[n0 * OUTD + tid];
        float v1 = g_Wh2[n1 * OUTD + tid];
        float v2 = g_Wh2[n2 * OUTD + tid];
        float v3 = g_Wh2[n3 * OUTD + tid];
        acc = fmaf(sw[j],   v0, acc);
        acc = fmaf(sw[j+1], v1, acc);
        acc = fmaf(sw[j+2], v2, acc);
        acc = fmaf(sw[j+3], v3, acc);
    }
    for (; j < deg; j++) acc = fmaf(sw[j], g_Wh2[snbr[j] * OUTD + tid], acc);
    out[i * OUTD + tid] = acc;
}

// ---------------- launcher ----------------
extern "C" void kernel_launch(void* const* d_in, const int* in_sizes, int n_in,
                              void* d_out, int out_size) {
    const float* adj = (const float*)d_in[0];
    const float* h   = (const float*)d_in[1];
    const float* W1  = (const float*)d_in[2];
    const float* a1s = (const float*)d_in[3];
    const float* a1d = (const float*)d_in[4];
    const float* W2  = (const float*)d_in[5];
    const float* a2s = (const float*)d_in[6];
    const float* a2d = (const float*)d_in[7];
    float* out = (float*)d_out;

    build_nbr<<<(NN + 7) / 8, 256>>>(adj);
    gemm1<<<NN, 128>>>(h, W1, a1s, a1d);
    agg1<<<NN, 128>>>();
    gemm2<<<NN, 64>>>(W2, a2s, a2d);
    agg2<<<NN, 64>>>(out);
}

// round 2
// speedup vs baseline: 1.6475x; 1.6475x over previous
#include <cuda_runtime.h>

#define NN 5000
#define IN_DIM 64
#define HID 32
#define NH 4
#define F1 (NH*HID)   // 128
#define OUTD 64
#define CAP 320
#define SWP 321       // padded stride (321 % 32 == 1 -> no 4-way bank conflict)
#define NEG_SLOPE 0.2f

// ---------------- device scratch ----------------
__device__ int   g_deg[NN];
__device__ int   g_nbr[NN * CAP];
__device__ __align__(16) float g_Wh1[NN * F1];
__device__ float g_s1src[NN * NH];
__device__ float g_s1dst[NN * NH];
__device__ __align__(16) float g_x[NN * F1];
__device__ __align__(16) float g_Wh2[NN * OUTD];
__device__ float g_s2src[NN];
__device__ float g_s2dst[NN];

// ---------------- 1) build neighbor lists (one warp/row, deterministic) ---
__global__ void build_nbr(const float* __restrict__ adj) {
    const int wpb = blockDim.x >> 5;
    const int row = blockIdx.x * wpb + (threadIdx.x >> 5);
    if (row >= NN) return;
    const int lane = threadIdx.x & 31;
    const float* __restrict__ r = adj + (size_t)row * NN;
    int base = 0;
    for (int c0 = 0; c0 < 4992; c0 += 128) {
        float4 v = *reinterpret_cast<const float4*>(r + c0 + lane * 4);
        int m = (v.x > 0.f) | ((v.y > 0.f) << 1) | ((v.z > 0.f) << 2) | ((v.w > 0.f) << 3);
        int cnt = __popc(m);
        int pref = cnt;
        #pragma unroll
        for (int d = 1; d < 32; d <<= 1) {
            int t = __shfl_up_sync(0xffffffffu, pref, d);
            if (lane >= d) pref += t;
        }
        int total = __shfl_sync(0xffffffffu, pref, 31);
        int o = base + (pref - cnt);
        int col = c0 + lane * 4;
        if (m & 1) { if (o < CAP) g_nbr[row * CAP + o] = col;     o++; }
        if (m & 2) { if (o < CAP) g_nbr[row * CAP + o] = col + 1; o++; }
        if (m & 4) { if (o < CAP) g_nbr[row * CAP + o] = col + 2; o++; }
        if (m & 8) { if (o < CAP) g_nbr[row * CAP + o] = col + 3; o++; }
        base += total;
    }
    {
        int c = 4992 + lane;
        int pred = (lane < 8) && (r[c] > 0.f);
        unsigned mk = __ballot_sync(0xffffffffu, pred);
        int pos = __popc(mk & ((1u << lane) - 1u));
        if (pred && base + pos < CAP) g_nbr[row * CAP + base + pos] = c;
        base += __popc(mk);
    }
    if (lane == 0) g_deg[row] = base < CAP ? base : CAP;
}

// ---------------- 2) tiled Wh1 = h @ W1 + fused s1 scores ----------------
// block: 256 threads, 32 nodes. warp ty owns nodes ty*4..ty*4+3; lane tx owns col quad.
__global__ void gemm1(const float* __restrict__ h, const float* __restrict__ W1,
                      const float* __restrict__ a1s, const float* __restrict__ a1d) {
    __shared__ float shh[32 * IN_DIM];   // 8 KB
    __shared__ float sW[IN_DIM * F1];    // 32 KB
    const int tid = threadIdx.x;
    const int node0 = blockIdx.x * 32;
    for (int i = tid; i < IN_DIM * F1 / 4; i += 256)
        ((float4*)sW)[i] = ((const float4*)W1)[i];
    for (int i = tid; i < 32 * IN_DIM / 4; i += 256) {
        int row = i >> 4;                 // 16 float4 per row
        float4 v = make_float4(0.f, 0.f, 0.f, 0.f);
        if (node0 + row < NN) v = ((const float4*)(h + (size_t)(node0 + row) * IN_DIM))[i & 15];
        ((float4*)shh)[i] = v;
    }
    __syncthreads();
    const int tx = tid & 31;   // col quad 0..31 (cols 4tx..4tx+3)
    const int ty = tid >> 5;   // warp 0..7
    float4 acc[4] = {};
    const float4* Wq = (const float4*)sW;
    #pragma unroll 8
    for (int k = 0; k < IN_DIM; k++) {
        float4 w = Wq[k * 32 + tx];
        #pragma unroll
        for (int m = 0; m < 4; m++) {
            float hv = shh[(ty * 4 + m) * IN_DIM + k];
            acc[m].x = fmaf(hv, w.x, acc[m].x);
            acc[m].y = fmaf(hv, w.y, acc[m].y);
            acc[m].z = fmaf(hv, w.z, acc[m].z);
            acc[m].w = fmaf(hv, w.w, acc[m].w);
        }
    }
    const float4 as = ((const float4*)a1s)[tx];   // a1 flattened [h][f] == col index
    const float4 ad = ((const float4*)a1d)[tx];
    #pragma unroll
    for (int m = 0; m < 4; m++) {
        const int node = node0 + ty * 4 + m;
        float ps = acc[m].x * as.x + acc[m].y * as.y + acc[m].z * as.z + acc[m].w * as.w;
        float pd = acc[m].x * ad.x + acc[m].y * ad.y + acc[m].z * ad.z + acc[m].w * ad.w;
        #pragma unroll
        for (int d = 4; d; d >>= 1) {   // reduce over 8-lane head group
            ps += __shfl_xor_sync(0xffffffffu, ps, d);
            pd += __shfl_xor_sync(0xffffffffu, pd, d);
        }
        if (node < NN) {
            ((float4*)(g_Wh1 + (size_t)node * F1))[tx] = acc[m];
            if ((tx & 7) == 0) {
                g_s1src[node * NH + (tx >> 3)] = ps;
                g_s1dst[node * NH + (tx >> 3)] = pd;
            }
        }
    }
}

// ---------------- 3) layer-1 sparse softmax-aggregate + ELU ----------------
__global__ void agg1() {
    const int i = blockIdx.x;
    const int tid = threadIdx.x;     // 128
    const int w = tid >> 5, lane = tid & 31;
    __shared__ int    snbr[CAP];
    __shared__ float  sw[NH * SWP];
    __shared__ float4 sacc[4][32];
    __shared__ int    sdeg;
    if (tid == 0) sdeg = g_deg[i];
    __syncthreads();
    const int deg = sdeg;
    for (int t = tid; t < deg; t += 128) snbr[t] = g_nbr[i * CAP + t];
    __syncthreads();
    for (int t = tid; t < deg * NH; t += 128) {
        int hh = t / deg, j = t - hh * deg;
        float e = g_s1src[i * NH + hh] + g_s1dst[snbr[j] * NH + hh];
        sw[hh * SWP + j] = e > 0.f ? e : NEG_SLOPE * e;
    }
    __syncthreads();
    {   // softmax: warp w owns head w
        float m = -1e30f;
        for (int j = lane; j < deg; j += 32) m = fmaxf(m, sw[w * SWP + j]);
        #pragma unroll
        for (int d = 16; d; d >>= 1) m = fmaxf(m, __shfl_xor_sync(0xffffffffu, m, d));
        float s = 0.f;
        for (int j = lane; j < deg; j += 32) s += __expf(sw[w * SWP + j] - m);
        #pragma unroll
        for (int d = 16; d; d >>= 1) s += __shfl_xor_sync(0xffffffffu, s, d);
        const float rinv = 1.f / s;
        for (int j = lane; j < deg; j += 32) sw[w * SWP + j] = __expf(sw[w * SWP + j] - m) * rinv;
    }
    __syncthreads();
    // gather: warp w handles neighbors j ≡ w (mod 4); lane = col quad; float4 loads
    const int hb = (lane >> 3) * SWP;
    float4 acc = {0.f, 0.f, 0.f, 0.f};
    int j = w;
    for (; j + 12 < deg; j += 16) {
        int n0 = snbr[j], n1 = snbr[j + 4], n2 = snbr[j + 8], n3 = snbr[j + 12];
        float w0 = sw[hb + j], w1 = sw[hb + j + 4], w2 = sw[hb + j + 8], w3 = sw[hb + j + 12];
        float4 v0 = *(const float4*)(g_Wh1 + (size_t)n0 * F1 + lane * 4);
        float4 v1 = *(const float4*)(g_Wh1 + (size_t)n1 * F1 + lane * 4);
        float4 v2 = *(const float4*)(g_Wh1 + (size_t)n2 * F1 + lane * 4);
        float4 v3 = *(const float4*)(g_Wh1 + (size_t)n3 * F1 + lane * 4);
        acc.x = fmaf(w0, v0.x, acc.x); acc.y = fmaf(w0, v0.y, acc.y);
        acc.z = fmaf(w0, v0.z, acc.z); acc.w = fmaf(w0, v0.w, acc.w);
        acc.x = fmaf(w1, v1.x, acc.x); acc.y = fmaf(w1, v1.y, acc.y);
        acc.z = fmaf(w1, v1.z, acc.z); acc.w = fmaf(w1, v1.w, acc.w);
        acc.x = fmaf(w2, v2.x, acc.x); acc.y = fmaf(w2, v2.y, acc.y);
        acc.z = fmaf(w2, v2.z, acc.z); acc.w = fmaf(w2, v2.w, acc.w);
        acc.x = fmaf(w3, v3.x, acc.x); acc.y = fmaf(w3, v3.y, acc.y);
        acc.z = fmaf(w3, v3.z, acc.z); acc.w = fmaf(w3, v3.w, acc.w);
    }
    for (; j < deg; j += 4) {
        float wt = sw[hb + j];
        float4 v = *(const float4*)(g_Wh1 + (size_t)snbr[j] * F1 + lane * 4);
        acc.x = fmaf(wt, v.x, acc.x); acc.y = fmaf(wt, v.y, acc.y);
        acc.z = fmaf(wt, v.z, acc.z); acc.w = fmaf(wt, v.w, acc.w);
    }
    sacc[w][lane] = acc;
    __syncthreads();
    if (tid < 32) {
        float4 a0 = sacc[0][tid], a1 = sacc[1][tid], a2 = sacc[2][tid], a3 = sacc[3][tid];
        float4 r;
        r.x = a0.x + a1.x + a2.x + a3.x;
        r.y = a0.y + a1.y + a2.y + a3.y;
        r.z = a0.z + a1.z + a2.z + a3.z;
        r.w = a0.w + a1.w + a2.w + a3.w;
        r.x = r.x > 0.f ? r.x : (__expf(r.x) - 1.f);
        r.y = r.y > 0.f ? r.y : (__expf(r.y) - 1.f);
        r.z = r.z > 0.f ? r.z : (__expf(r.z) - 1.f);
        r.w = r.w > 0.f ? r.w : (__expf(r.w) - 1.f);
        ((float4*)(g_x + (size_t)i * F1))[tid] = r;
    }
}

// ---------------- 4) tiled Wh2 = x @ W2 + fused s2 scores ----------------
// block: 256 threads, 32 nodes. group ty (16 lanes) owns nodes ty, ty+16; lane tx owns col quad.
__global__ void gemm2(const float* __restrict__ W2,
                      const float* __restrict__ a2s, const float* __restrict__ a2d) {
    __shared__ float sx[32 * F1];      // 16 KB
    __shared__ float sW[F1 * OUTD];    // 32 KB
    const int tid = threadIdx.x;
    const int node0 = blockIdx.x * 32;
    for (int i = tid; i < F1 * OUTD / 4; i += 256)
        ((float4*)sW)[i] = ((const float4*)W2)[i];
    for (int i = tid; i < 32 * F1 / 4; i += 256) {
        int row = i >> 5;              // 32 float4 per row
        float4 v = make_float4(0.f, 0.f, 0.f, 0.f);
        if (node0 + row < NN) v = ((const float4*)(g_x + (size_t)(node0 + row) * F1))[i & 31];
        ((float4*)sx)[i] = v;
    }
    __syncthreads();
    const int tx = tid & 15;   // col quad 0..15 (cols 4tx..4tx+3)
    const int ty = tid >> 4;   // group 0..15, nodes ty and ty+16
    float4 acc0 = {}, acc1 = {};
    const float4* Wq = (const float4*)sW;
    #pragma unroll 8
    for (int k = 0; k < F1; k++) {
        float4 w = Wq[k * 16 + tx];
        float h0 = sx[ty * F1 + k];
        float h1 = sx[(ty + 16) * F1 + k];
        acc0.x = fmaf(h0, w.x, acc0.x); acc0.y = fmaf(h0, w.y, acc0.y);
        acc0.z = fmaf(h0, w.z, acc0.z); acc0.w = fmaf(h0, w.w, acc0.w);
        acc1.x = fmaf(h1, w.x, acc1.x); acc1.y = fmaf(h1, w.y, acc1.y);
        acc1.z = fmaf(h1, w.z, acc1.z); acc1.w = fmaf(h1, w.w, acc1.w);
    }
    const float4 as = ((const float4*)a2s)[tx];
    const float4 ad = ((const float4*)a2d)[tx];
    #pragma unroll
    for (int m = 0; m < 2; m++) {
        const float4 a = m ? acc1 : acc0;
        const int node = node0 + ty + m * 16;
        float ps = a.x * as.x + a.y * as.y + a.z * as.z + a.w * as.w;
        float pd = a.x * ad.x + a.y * ad.y + a.z * ad.z + a.w * ad.w;
        #pragma unroll
        for (int d = 8; d; d >>= 1) {   // reduce over 16-lane group
            ps += __shfl_xor_sync(0xffffffffu, ps, d);
            pd += __shfl_xor_sync(0xffffffffu, pd, d);
        }
        if (node < NN) {
            ((float4*)(g_Wh2 + (size_t)node * OUTD))[tx] = a;
            if (tx == 0) { g_s2src[node] = ps; g_s2dst[node] = pd; }
        }
    }
}

// ---------------- 5) layer-2 sparse softmax-aggregate -> out ----------------
__global__ void agg2(float* __restrict__ out) {
    const int i = blockIdx.x;
    const int tid = threadIdx.x;     // 64
    const int g = tid >> 4, l = tid & 15;
    __shared__ int    snbr[CAP];
    __shared__ float  sw[CAP];
    __shared__ float4 sacc[4][16];
    __shared__ int    sdeg;
    if (tid == 0) sdeg = g_deg[i];
    __syncthreads();
    const int deg = sdeg;
    for (int t = tid; t < deg; t += 64) snbr[t] = g_nbr[i * CAP + t];
    __syncthreads();
    const float ssrc = g_s2src[i];
    for (int t = tid; t < deg; t += 64) {
        float e = ssrc + g_s2dst[snbr[t]];
        sw[t] = e > 0.f ? e : NEG_SLOPE * e;
    }
    __syncthreads();
    if (tid < 32) {
        float m = -1e30f;
        for (int j = tid; j < deg; j += 32) m = fmaxf(m, sw[j]);
        #pragma unroll
        for (int d = 16; d; d >>= 1) m = fmaxf(m, __shfl_xor_sync(0xffffffffu, m, d));
        float s = 0.f;
        for (int j = tid; j < deg; j += 32) s += __expf(sw[j] - m);
        #pragma unroll
        for (int d = 16; d; d >>= 1) s += __shfl_xor_sync(0xffffffffu, s, d);
        const float rinv = 1.f / s;
        for (int j = tid; j < deg; j += 32) sw[j] = __expf(sw[j] - m) * rinv;
    }
    __syncthreads();
    // gather: group g handles neighbors j ≡ g (mod 4); lane l = col quad; float4 loads
    float4 acc = {0.f, 0.f, 0.f, 0.f};
    int j = g;
    for (; j + 12 < deg; j += 16) {
        int n0 = snbr[j], n1 = snbr[j + 4], n2 = snbr[j + 8], n3 = snbr[j + 12];
        float w0 = sw[j], w1 = sw[j + 4], w2 = sw[j + 8], w3 = sw[j + 12];
        float4 v0 = *(const float4*)(g_Wh2 + (size_t)n0 * OUTD + l * 4);
        float4 v1 = *(const float4*)(g_Wh2 + (size_t)n1 * OUTD + l * 4);
        float4 v2 = *(const float4*)(g_Wh2 + (size_t)n2 * OUTD + l * 4);
        float4 v3 = *(const float4*)(g_Wh2 + (size_t)n3 * OUTD + l * 4);
        acc.x = fmaf(w0, v0.x, acc.x); acc.y = fmaf(w0, v0.y, acc.y);
        acc.z = fmaf(w0, v0.z, acc.z); acc.w = fmaf(w0, v0.w, acc.w);
        acc.x = fmaf(w1, v1.x, acc.x); acc.y = fmaf(w1, v1.y, acc.y);
        acc.z = fmaf(w1, v1.z, acc.z); acc.w = fmaf(w1, v1.w, acc.w);
        acc.x = fmaf(w2, v2.x, acc.x); acc.y = fmaf(w2, v2.y, acc.y);
        acc.z = fmaf(w2, v2.z, acc.z); acc.w = fmaf(w2, v2.w, acc.w);
        acc.x = fmaf(w3, v3.x, acc.x); acc.y = fmaf(w3, v3.y, acc.y);
        acc.z = fmaf(w3, v3.z, acc.z); acc.w = fmaf(w3, v3.w, acc.w);
    }
    for (; j < deg; j += 4) {
        float wt = sw[j];
        float4 v = *(const float4*)(g_Wh2 + (size_t)snbr[j] * OUTD + l * 4);
        acc.x = fmaf(wt, v.x, acc.x); acc.y = fmaf(wt, v.y, acc.y);
        acc.z = fmaf(wt, v.z, acc.z); acc.w = fmaf(wt, v.w, acc.w);
    }
    sacc[g][l] = acc;
    __syncthreads();
    if (tid < 16) {
        float4 a0 = sacc[0][tid], a1 = sacc[1][tid], a2 = sacc[2][tid], a3 = sacc[3][tid];
        float4 r;
        r.x = a0.x + a1.x + a2.x + a3.x;
        r.y = a0.y + a1.y + a2.y + a3.y;
        r.z = a0.z + a1.z + a2.z + a3.z;
        r.w = a0.w + a1.w + a2.w + a3.w;
        ((float4*)(out + (size_t)i * OUTD))[tid] = r;
    }
}

// ---------------- launcher ----------------
extern "C" void kernel_launch(void* const* d_in, const int* in_sizes, int n_in,
                              void* d_out, int out_size) {
    const float* adj = (const float*)d_in[0];
    const float* h   = (const float*)d_in[1];
    const float* W1  = (const float*)d_in[2];
    const float* a1s = (const float*)d_in[3];
    const float* a1d = (const float*)d_in[4];
    const float* W2  = (const float*)d_in[5];
    const float* a2s = (const float*)d_in[6];
    const float* a2d = (const float*)d_in[7];
    float* out = (float*)d_out;

    build_nbr<<<(NN + 7) / 8, 256>>>(adj);
    gemm1<<<(NN + 31) / 32, 256>>>(h, W1, a1s, a1d);
    agg1<<<NN, 128>>>();
    gemm2<<<(NN + 31) / 32, 256>>>(W2, a2s, a2d);
    agg2<<<NN, 64>>>(out);
}

// round 3
// speedup vs baseline: 1.9861x; 1.2056x over previous
#include <cuda_runtime.h>
#include <cuda_fp16.h>

#define NN 5000
#define IN_DIM 64
#define HID 32
#define NH 4
#define F1 (NH*HID)   // 128
#define OUTD 64
#define CAP 320
#define SWP 321       // padded stride (no 4-way bank conflict)
#define NEG_SLOPE 0.2f

// ---------------- device scratch ----------------
__device__ int   g_deg[NN];
__device__ int   g_nbr[NN * CAP];
__device__ __align__(16) __half g_Wh1h[NN * F1];   // fp16 copy for gather
__device__ float g_s1src[NN * NH];
__device__ float g_s1dst[NN * NH];
__device__ __align__(16) __half g_Wh2h[NN * OUTD]; // fp16 copy for gather
__device__ float g_s2src[NN];
__device__ float g_s2dst[NN];

// ---------------- 1) build neighbor lists (one warp/row, deterministic) ---
__global__ void build_nbr(const float* __restrict__ adj) {
    const int wpb = blockDim.x >> 5;
    const int row = blockIdx.x * wpb + (threadIdx.x >> 5);
    if (row >= NN) return;
    const int lane = threadIdx.x & 31;
    const float* __restrict__ r = adj + (size_t)row * NN;
    int base = 0;
    float4 v = *reinterpret_cast<const float4*>(r + lane * 4);   // prefetch
    for (int c0 = 0; c0 < 4992; c0 += 128) {
        float4 vn = make_float4(0.f, 0.f, 0.f, 0.f);
        if (c0 + 128 < 4992)
            vn = *reinterpret_cast<const float4*>(r + c0 + 128 + lane * 4);
        int m = (v.x > 0.f) | ((v.y > 0.f) << 1) | ((v.z > 0.f) << 2) | ((v.w > 0.f) << 3);
        int cnt = __popc(m);
        int pref = cnt;
        #pragma unroll
        for (int d = 1; d < 32; d <<= 1) {
            int t = __shfl_up_sync(0xffffffffu, pref, d);
            if (lane >= d) pref += t;
        }
        int total = __shfl_sync(0xffffffffu, pref, 31);
        int o = base + (pref - cnt);
        int col = c0 + lane * 4;
        if (m & 1) { if (o < CAP) g_nbr[row * CAP + o] = col;     o++; }
        if (m & 2) { if (o < CAP) g_nbr[row * CAP + o] = col + 1; o++; }
        if (m & 4) { if (o < CAP) g_nbr[row * CAP + o] = col + 2; o++; }
        if (m & 8) { if (o < CAP) g_nbr[row * CAP + o] = col + 3; o++; }
        base += total;
        v = vn;
    }
    {
        int c = 4992 + lane;
        int pred = (lane < 8) && (r[c] > 0.f);
        unsigned mk = __ballot_sync(0xffffffffu, pred);
        int pos = __popc(mk & ((1u << lane) - 1u));
        if (pred && base + pos < CAP) g_nbr[row * CAP + base + pos] = c;
        base += __popc(mk);
    }
    if (lane == 0) g_deg[row] = base < CAP ? base : CAP;
}

// ---------------- 2) Wh1 = h @ W1 (8 nodes/block), fused s1, fp16 out ------
__global__ __launch_bounds__(256) void gemm1(
        const float* __restrict__ h, const float* __restrict__ W1,
        const float* __restrict__ a1s, const float* __restrict__ a1d) {
    __shared__ float sW[IN_DIM * F1];   // 32 KB
    __shared__ float shh[8 * IN_DIM];   // 2 KB
    const int tid = threadIdx.x;
    const int node0 = blockIdx.x * 8;   // 5000 = 625*8, exact
    #pragma unroll
    for (int i = 0; i < 8; i++)
        ((float4*)sW)[tid + i * 256] = ((const float4*)W1)[tid + i * 256];
    if (tid < 128)
        ((float4*)shh)[tid] = ((const float4*)(h + (size_t)node0 * IN_DIM))[tid];
    __syncthreads();
    const int tx = tid & 31;   // col quad (cols 4tx..4tx+3)
    const int ty = tid >> 5;   // node within tile
    const int node = node0 + ty;
    float4 acc = {0.f, 0.f, 0.f, 0.f};
    const float4* Wq = (const float4*)sW;
    #pragma unroll 16
    for (int k = 0; k < IN_DIM; k++) {
        float4 w = Wq[k * 32 + tx];
        float hv = shh[ty * IN_DIM + k];
        acc.x = fmaf(hv, w.x, acc.x); acc.y = fmaf(hv, w.y, acc.y);
        acc.z = fmaf(hv, w.z, acc.z); acc.w = fmaf(hv, w.w, acc.w);
    }
    // fp16 store for gather
    __half2* dst = (__half2*)(g_Wh1h + (size_t)node * F1);
    dst[tx * 2]     = __floats2half2_rn(acc.x, acc.y);
    dst[tx * 2 + 1] = __floats2half2_rn(acc.z, acc.w);
    // fused attention scores (fp32 accumulators)
    const float4 as = ((const float4*)a1s)[tx];
    const float4 ad = ((const float4*)a1d)[tx];
    float ps = acc.x * as.x + acc.y * as.y + acc.z * as.z + acc.w * as.w;
    float pd = acc.x * ad.x + acc.y * ad.y + acc.z * ad.z + acc.w * ad.w;
    #pragma unroll
    for (int d = 4; d; d >>= 1) {   // reduce over 8-lane head group
        ps += __shfl_xor_sync(0xffffffffu, ps, d);
        pd += __shfl_xor_sync(0xffffffffu, pd, d);
    }
    if ((tx & 7) == 0) {
        g_s1src[node * NH + (tx >> 3)] = ps;
        g_s1dst[node * NH + (tx >> 3)] = pd;
    }
}

// ---------------- 3) fused: layer-1 agg + ELU + x@W2 + s2 scores ----------
__global__ __launch_bounds__(128) void agg1_gemm2(
        const float* __restrict__ W2,
        const float* __restrict__ a2s, const float* __restrict__ a2d) {
    const int i = blockIdx.x;
    const int tid = threadIdx.x;     // 128
    const int w = tid >> 5, lane = tid & 31;
    __shared__ int    snbr[CAP];
    __shared__ float  swt[NH * SWP];
    __shared__ float4 sacc[4][32];
    __shared__ float  sx[F1];        // ELU'd x row
    __shared__ float4 spart[8][16];  // split-k partials for x@W2
    __shared__ int    sdeg;
    if (tid == 0) sdeg = g_deg[i];
    __syncthreads();
    const int deg = sdeg;
    for (int t = tid; t < deg; t += 128) snbr[t] = g_nbr[i * CAP + t];
    __syncthreads();
    for (int t = tid; t < deg * NH; t += 128) {
        int hh = t / deg, j = t - hh * deg;
        float e = g_s1src[i * NH + hh] + g_s1dst[snbr[j] * NH + hh];
        swt[hh * SWP + j] = e > 0.f ? e : NEG_SLOPE * e;
    }
    __syncthreads();
    {   // softmax: warp w owns head w
        float m = -1e30f;
        for (int j = lane; j < deg; j += 32) m = fmaxf(m, swt[w * SWP + j]);
        #pragma unroll
        for (int d = 16; d; d >>= 1) m = fmaxf(m, __shfl_xor_sync(0xffffffffu, m, d));
        float s = 0.f;
        for (int j = lane; j < deg; j += 32) s += __expf(swt[w * SWP + j] - m);
        #pragma unroll
        for (int d = 16; d; d >>= 1) s += __shfl_xor_sync(0xffffffffu, s, d);
        const float rinv = 1.f / s;
        for (int j = lane; j < deg; j += 32) swt[w * SWP + j] = __expf(swt[w * SWP + j] - m) * rinv;
    }
    __syncthreads();
    // gather fp16 Wh1: warp w takes j ≡ w (mod 4); lane covers cols 4lane..4lane+3
    const int hb = (lane >> 3) * SWP;
    float4 acc = {0.f, 0.f, 0.f, 0.f};
    int j = w;
    for (; j + 12 < deg; j += 16) {
        int n0 = snbr[j], n1 = snbr[j + 4], n2 = snbr[j + 8], n3 = snbr[j + 12];
        float w0 = swt[hb + j], w1 = swt[hb + j + 4], w2 = swt[hb + j + 8], w3 = swt[hb + j + 12];
        uint2 r0 = *(const uint2*)(g_Wh1h + (size_t)n0 * F1 + lane * 4);
        uint2 r1 = *(const uint2*)(g_Wh1h + (size_t)n1 * F1 + lane * 4);
        uint2 r2 = *(const uint2*)(g_Wh1h + (size_t)n2 * F1 + lane * 4);
        uint2 r3 = *(const uint2*)(g_Wh1h + (size_t)n3 * F1 + lane * 4);
        float2 a0 = __half22float2(*(__half2*)&r0.x), b0 = __half22float2(*(__half2*)&r0.y);
        float2 a1 = __half22float2(*(__half2*)&r1.x), b1 = __half22float2(*(__half2*)&r1.y);
        float2 a2 = __half22float2(*(__half2*)&r2.x), b2 = __half22float2(*(__half2*)&r2.y);
        float2 a3 = __half22float2(*(__half2*)&r3.x), b3 = __half22float2(*(__half2*)&r3.y);
        acc.x = fmaf(w0, a0.x, acc.x); acc.y = fmaf(w0, a0.y, acc.y);
        acc.z = fmaf(w0, b0.x, acc.z); acc.w = fmaf(w0, b0.y, acc.w);
        acc.x = fmaf(w1, a1.x, acc.x); acc.y = fmaf(w1, a1.y, acc.y);
        acc.z = fmaf(w1, b1.x, acc.z); acc.w = fmaf(w1, b1.y, acc.w);
        acc.x = fmaf(w2, a2.x, acc.x); acc.y = fmaf(w2, a2.y, acc.y);
        acc.z = fmaf(w2, b2.x, acc.z); acc.w = fmaf(w2, b2.y, acc.w);
        acc.x = fmaf(w3, a3.x, acc.x); acc.y = fmaf(w3, a3.y, acc.y);
        acc.z = fmaf(w3, b3.x, acc.z); acc.w = fmaf(w3, b3.y, acc.w);
    }
    for (; j < deg; j += 4) {
        float wt = swt[hb + j];
        uint2 rr = *(const uint2*)(g_Wh1h + (size_t)snbr[j] * F1 + lane * 4);
        float2 aa = __half22float2(*(__half2*)&rr.x), bb = __half22float2(*(__half2*)&rr.y);
        acc.x = fmaf(wt, aa.x, acc.x); acc.y = fmaf(wt, aa.y, acc.y);
        acc.z = fmaf(wt, bb.x, acc.z); acc.w = fmaf(wt, bb.y, acc.w);
    }
    sacc[w][lane] = acc;
    __syncthreads();
    if (tid < 32) {   // reduce 4 warps, ELU, publish x row
        float4 a0 = sacc[0][tid], a1 = sacc[1][tid], a2 = sacc[2][tid], a3 = sacc[3][tid];
        float4 r;
        r.x = a0.x + a1.x + a2.x + a3.x;
        r.y = a0.y + a1.y + a2.y + a3.y;
        r.z = a0.z + a1.z + a2.z + a3.z;
        r.w = a0.w + a1.w + a2.w + a3.w;
        r.x = r.x > 0.f ? r.x : (__expf(r.x) - 1.f);
        r.y = r.y > 0.f ? r.y : (__expf(r.y) - 1.f);
        r.z = r.z > 0.f ? r.z : (__expf(r.z) - 1.f);
        r.w = r.w > 0.f ? r.w : (__expf(r.w) - 1.f);
        ((float4*)sx)[tid] = r;
    }
    __syncthreads();
    // fused gemm2: Wh2[i] = sx @ W2 (128x64), split-k: c = k-chunk, q = col quad
    {
        const int q = tid & 15;    // col quad 0..15
        const int c = tid >> 4;    // k chunk 0..7
        float4 a = {0.f, 0.f, 0.f, 0.f};
        const float4* Wq = (const float4*)W2;
        #pragma unroll
        for (int kk = 0; kk < 16; kk++) {
            int k = c * 16 + kk;
            float4 w4 = Wq[k * 16 + q];
            float xv = sx[k];
            a.x = fmaf(xv, w4.x, a.x); a.y = fmaf(xv, w4.y, a.y);
            a.z = fmaf(xv, w4.z, a.z); a.w = fmaf(xv, w4.w, a.w);
        }
        spart[c][q] = a;
    }
    __syncthreads();
    if (tid < 16) {
        float4 r = {0.f, 0.f, 0.f, 0.f};
        #pragma unroll
        for (int c = 0; c < 8; c++) {
            float4 p = spart[c][tid];
            r.x += p.x; r.y += p.y; r.z += p.z; r.w += p.w;
        }
        __half2* dst = (__half2*)(g_Wh2h + (size_t)i * OUTD);
        dst[tid * 2]     = __floats2half2_rn(r.x, r.y);
        dst[tid * 2 + 1] = __floats2half2_rn(r.z, r.w);
        const float4 as = ((const float4*)a2s)[tid];
        const float4 ad = ((const float4*)a2d)[tid];
        float ps = r.x * as.x + r.y * as.y + r.z * as.z + r.w * as.w;
        float pd = r.x * ad.x + r.y * ad.y + r.z * ad.z + r.w * ad.w;
        #pragma unroll
        for (int d = 8; d; d >>= 1) {
            ps += __shfl_xor_sync(0xffffu, ps, d);
            pd += __shfl_xor_sync(0xffffu, pd, d);
        }
        if (tid == 0) { g_s2src[i] = ps; g_s2dst[i] = pd; }
    }
}

// ---------------- 4) layer-2 sparse softmax-aggregate -> out ----------------
__global__ __launch_bounds__(64) void agg2(float* __restrict__ out) {
    const int i = blockIdx.x;
    const int tid = threadIdx.x;     // 64
    const int g = tid >> 4, l = tid & 15;
    __shared__ int    snbr[CAP];
    __shared__ float  sw[CAP];
    __shared__ float4 sacc[4][16];
    __shared__ int    sdeg;
    if (tid == 0) sdeg = g_deg[i];
    __syncthreads();
    const int deg = sdeg;
    for (int t = tid; t < deg; t += 64) snbr[t] = g_nbr[i * CAP + t];
    __syncthreads();
    const float ssrc = g_s2src[i];
    for (int t = tid; t < deg; t += 64) {
        float e = ssrc + g_s2dst[snbr[t]];
        sw[t] = e > 0.f ? e : NEG_SLOPE * e;
    }
    __syncthreads();
    if (tid < 32) {
        float m = -1e30f;
        for (int j = tid; j < deg; j += 32) m = fmaxf(m, sw[j]);
        #pragma unroll
        for (int d = 16; d; d >>= 1) m = fmaxf(m, __shfl_xor_sync(0xffffffffu, m, d));
        float s = 0.f;
        for (int j = tid; j < deg; j += 32) s += __expf(sw[j] - m);
        #pragma unroll
        for (int d = 16; d; d >>= 1) s += __shfl_xor_sync(0xffffffffu, s, d);
        const float rinv = 1.f / s;
        for (int j = tid; j < deg; j += 32) sw[j] = __expf(sw[j] - m) * rinv;
    }
    __syncthreads();
    // gather fp16 Wh2: group g takes j ≡ g (mod 4); lane l covers cols 4l..4l+3
    float4 acc = {0.f, 0.f, 0.f, 0.f};
    int j = g;
    for (; j + 12 < deg; j += 16) {
        int n0 = snbr[j], n1 = snbr[j + 4], n2 = snbr[j + 8], n3 = snbr[j + 12];
        float w0 = sw[j], w1 = sw[j + 4], w2 = sw[j + 8], w3 = sw[j + 12];
        uint2 r0 = *(const uint2*)(g_Wh2h + (size_t)n0 * OUTD + l * 4);
        uint2 r1 = *(const uint2*)(g_Wh2h + (size_t)n1 * OUTD + l * 4);
        uint2 r2 = *(const uint2*)(g_Wh2h + (size_t)n2 * OUTD + l * 4);
        uint2 r3 = *(const uint2*)(g_Wh2h + (size_t)n3 * OUTD + l * 4);
        float2 a0 = __half22float2(*(__half2*)&r0.x), b0 = __half22float2(*(__half2*)&r0.y);
        float2 a1 = __half22float2(*(__half2*)&r1.x), b1 = __half22float2(*(__half2*)&r1.y);
        float2 a2 = __half22float2(*(__half2*)&r2.x), b2 = __half22float2(*(__half2*)&r2.y);
        float2 a3 = __half22float2(*(__half2*)&r3.x), b3 = __half22float2(*(__half2*)&r3.y);
        acc.x = fmaf(w0, a0.x, acc.x); acc.y = fmaf(w0, a0.y, acc.y);
        acc.z = fmaf(w0, b0.x, acc.z); acc.w = fmaf(w0, b0.y, acc.w);
        acc.x = fmaf(w1, a1.x, acc.x); acc.y = fmaf(w1, a1.y, acc.y);
        acc.z = fmaf(w1, b1.x, acc.z); acc.w = fmaf(w1, b1.y, acc.w);
        acc.x = fmaf(w2, a2.x, acc.x); acc.y = fmaf(w2, a2.y, acc.y);
        acc.z = fmaf(w2, b2.x, acc.z); acc.w = fmaf(w2, b2.y, acc.w);
        acc.x = fmaf(w3, a3.x, acc.x); acc.y = fmaf(w3, a3.y, acc.y);
        acc.z = fmaf(w3, b3.x, acc.z); acc.w = fmaf(w3, b3.y, acc.w);
    }
    for (; j < deg; j += 4) {
        float wt = sw[j];
        uint2 rr = *(const uint2*)(g_Wh2h + (size_t)snbr[j] * OUTD + l * 4);
        float2 aa = __half22float2(*(__half2*)&rr.x), bb = __half22float2(*(__half2*)&rr.y);
        acc.x = fmaf(wt, aa.x, acc.x); acc.y = fmaf(wt, aa.y, acc.y);
        acc.z = fmaf(wt, bb.x, acc.z); acc.w = fmaf(wt, bb.y, acc.w);
    }
    sacc[g][l] = acc;
    __syncthreads();
    if (tid < 16) {
        float4 a0 = sacc[0][tid], a1 = sacc[1][tid], a2 = sacc[2][tid], a3 = sacc[3][tid];
        float4 r;
        r.x = a0.x + a1.x + a2.x + a3.x;
        r.y = a0.y + a1.y + a2.y + a3.y;
        r.z = a0.z + a1.z + a2.z + a3.z;
        r.w = a0.w + a1.w + a2.w + a3.w;
        ((float4*)(out + (size_t)i * OUTD))[tid] = r;
    }
}

// ---------------- launcher ----------------
extern "C" void kernel_launch(void* const* d_in, const int* in_sizes, int n_in,
                              void* d_out, int out_size) {
    const float* adj = (const float*)d_in[0];
    const float* h   = (const float*)d_in[1];
    const float* W1  = (const float*)d_in[2];
    const float* a1s = (const float*)d_in[3];
    const float* a1d = (const float*)d_in[4];
    const float* W2  = (const float*)d_in[5];
    const float* a2s = (const float*)d_in[6];
    const float* a2d = (const float*)d_in[7];
    float* out = (float*)d_out;

    build_nbr<<<(NN + 7) / 8, 256>>>(adj);
    gemm1<<<NN / 8, 256>>>(h, W1, a1s, a1d);
    agg1_gemm2<<<NN, 128>>>(W2, a2s, a2d);
    agg2<<<NN, 64>>>(out);
}

// round 4
// speedup vs baseline: 2.1056x; 1.0602x over previous
#include <cuda_runtime.h>
#include <cuda_fp16.h>

#define NN 5000
#define IN_DIM 64
#define HID 32
#define NH 4
#define F1 (NH*HID)   // 128
#define OUTD 64
#define CAP 320
#define SWP 321       // padded stride (no 4-way bank conflict)
#define NEG_SLOPE 0.2f

// ---------------- device scratch ----------------
__device__ int   g_deg[NN];
__device__ int   g_nbr[NN * CAP];
__device__ __align__(16) __half g_Wh1h[NN * F1];   // fp16 for gather
__device__ float g_s1src[NN * NH];
__device__ float g_s1dst[NN * NH];
__device__ __align__(16) __half g_Wh2h[NN * OUTD]; // fp16 for gather
__device__ float g_s2src[NN];
__device__ float g_s2dst[NN];

// ---------------- 1) fused: build neighbor lists + gemm1 ----------------
// blocks [0,625): build (8 rows/block, 1 warp/row). blocks [625,1250): gemm1 (8 nodes/block).
__global__ __launch_bounds__(256) void build_and_gemm1(
        const float* __restrict__ adj, const float* __restrict__ h,
        const float* __restrict__ W1,
        const float* __restrict__ a1s, const float* __restrict__ a1d) {
    const int tid = threadIdx.x;
    if (blockIdx.x < 625) {
        // ---- build_nbr ----
        const int row = blockIdx.x * 8 + (tid >> 5);
        const int lane = tid & 31;
        const float* __restrict__ r = adj + (size_t)row * NN;
        int base = 0;
        float4 v = *reinterpret_cast<const float4*>(r + lane * 4);   // prefetch
        for (int c0 = 0; c0 < 4992; c0 += 128) {
            float4 vn = make_float4(0.f, 0.f, 0.f, 0.f);
            if (c0 + 128 < 4992)
                vn = *reinterpret_cast<const float4*>(r + c0 + 128 + lane * 4);
            int m = (v.x > 0.f) | ((v.y > 0.f) << 1) | ((v.z > 0.f) << 2) | ((v.w > 0.f) << 3);
            int cnt = __popc(m);
            int pref = cnt;
            #pragma unroll
            for (int d = 1; d < 32; d <<= 1) {
                int t = __shfl_up_sync(0xffffffffu, pref, d);
                if (lane >= d) pref += t;
            }
            int total = __shfl_sync(0xffffffffu, pref, 31);
            int o = base + (pref - cnt);
            int col = c0 + lane * 4;
            if (m & 1) { if (o < CAP) g_nbr[row * CAP + o] = col;     o++; }
            if (m & 2) { if (o < CAP) g_nbr[row * CAP + o] = col + 1; o++; }
            if (m & 4) { if (o < CAP) g_nbr[row * CAP + o] = col + 2; o++; }
            if (m & 8) { if (o < CAP) g_nbr[row * CAP + o] = col + 3; o++; }
            base += total;
            v = vn;
        }
        {
            int c = 4992 + lane;
            int pred = (lane < 8) && (r[c] > 0.f);
            unsigned mk = __ballot_sync(0xffffffffu, pred);
            int pos = __popc(mk & ((1u << lane) - 1u));
            if (pred && base + pos < CAP) g_nbr[row * CAP + base + pos] = c;
            base += __popc(mk);
        }
        if (lane == 0) g_deg[row] = base < CAP ? base : CAP;
    } else {
        // ---- gemm1: Wh1 = h @ W1, fused s1 scores, fp16 out ----
        __shared__ float sW[IN_DIM * F1];   // 32 KB
        __shared__ float shh[8 * IN_DIM];   // 2 KB
        const int node0 = (blockIdx.x - 625) * 8;
        #pragma unroll
        for (int i = 0; i < 8; i++)
            ((float4*)sW)[tid + i * 256] = ((const float4*)W1)[tid + i * 256];
        if (tid < 128)
            ((float4*)shh)[tid] = ((const float4*)(h + (size_t)node0 * IN_DIM))[tid];
        __syncthreads();
        const int tx = tid & 31;   // col quad
        const int ty = tid >> 5;   // node within tile
        const int node = node0 + ty;
        float4 acc = {0.f, 0.f, 0.f, 0.f};
        const float4* Wq = (const float4*)sW;
        #pragma unroll 16
        for (int k = 0; k < IN_DIM; k++) {
            float4 w = Wq[k * 32 + tx];
            float hv = shh[ty * IN_DIM + k];
            acc.x = fmaf(hv, w.x, acc.x); acc.y = fmaf(hv, w.y, acc.y);
            acc.z = fmaf(hv, w.z, acc.z); acc.w = fmaf(hv, w.w, acc.w);
        }
        __half2* dst = (__half2*)(g_Wh1h + (size_t)node * F1);
        dst[tx * 2]     = __floats2half2_rn(acc.x, acc.y);
        dst[tx * 2 + 1] = __floats2half2_rn(acc.z, acc.w);
        const float4 as = ((const float4*)a1s)[tx];
        const float4 ad = ((const float4*)a1d)[tx];
        float ps = acc.x * as.x + acc.y * as.y + acc.z * as.z + acc.w * as.w;
        float pd = acc.x * ad.x + acc.y * ad.y + acc.z * ad.z + acc.w * ad.w;
        #pragma unroll
        for (int d = 4; d; d >>= 1) {
            ps += __shfl_xor_sync(0xffffffffu, ps, d);
            pd += __shfl_xor_sync(0xffffffffu, pd, d);
        }
        if ((tx & 7) == 0) {
            g_s1src[node * NH + (tx >> 3)] = ps;
            g_s1dst[node * NH + (tx >> 3)] = pd;
        }
    }
}

// ---------------- 2) fused: layer-1 agg + ELU + x@W2 + s2 scores ----------
__global__ __launch_bounds__(128) void agg1_gemm2(
        const float* __restrict__ W2,
        const float* __restrict__ a2s, const float* __restrict__ a2d) {
    const int i = blockIdx.x;
    const int tid = threadIdx.x;     // 128
    const int w = tid >> 5, lane = tid & 31;
    __shared__ int    snbr[CAP];
    __shared__ float  swt[NH * SWP];
    __shared__ float  sred[8][F1];   // gather partials (4 KB)
    __shared__ float  sx[F1];        // ELU'd x row
    __shared__ float4 spart[8][16];  // split-k partials for x@W2
    __shared__ int    sdeg;
    if (tid == 0) sdeg = g_deg[i];
    __syncthreads();
    const int deg = sdeg;
    for (int t = tid; t < deg; t += 128) snbr[t] = g_nbr[i * CAP + t];
    __syncthreads();
    // scores: warp w owns head w (no integer division)
    {
        const float ssrc = g_s1src[i * NH + w];
        for (int j = lane; j < deg; j += 32) {
            float e = ssrc + g_s1dst[snbr[j] * NH + w];
            swt[w * SWP + j] = e > 0.f ? e : NEG_SLOPE * e;
        }
    }
    __syncthreads();
    {   // softmax: warp w owns head w
        float m = -1e30f;
        for (int j = lane; j < deg; j += 32) m = fmaxf(m, swt[w * SWP + j]);
        #pragma unroll
        for (int d = 16; d; d >>= 1) m = fmaxf(m, __shfl_xor_sync(0xffffffffu, m, d));
        float s = 0.f;
        for (int j = lane; j < deg; j += 32) s += __expf(swt[w * SWP + j] - m);
        #pragma unroll
        for (int d = 16; d; d >>= 1) s += __shfl_xor_sync(0xffffffffu, s, d);
        const float rinv = 1.f / s;
        for (int j = lane; j < deg; j += 32) swt[w * SWP + j] = __expf(swt[w * SWP + j] - m) * rinv;
    }
    __syncthreads();
    // gather fp16 Wh1 with LDG.128: 16 lanes/row, 2 rows per warp in flight
    {
        const int half = lane >> 4;          // 0/1: which row within warp
        const int q = lane & 15;             // uint4 index within row (8 halfs)
        const int head = q >> 2;             // cols q*8.. are in head q/4
        const int grp = w * 2 + half;        // 0..7
        const float* __restrict__ wrow = swt + head * SWP;
        float a0=0.f,a1=0.f,a2=0.f,a3=0.f,a4=0.f,a5=0.f,a6=0.f,a7=0.f;
        int j = grp;
        for (; j + 8 < deg; j += 16) {
            int na = snbr[j], nb = snbr[j + 8];
            float wa = wrow[j], wb = wrow[j + 8];
            uint4 ra = *(const uint4*)(g_Wh1h + (size_t)na * F1 + q * 8);
            uint4 rb = *(const uint4*)(g_Wh1h + (size_t)nb * F1 + q * 8);
            float2 p;
            p = __half22float2(*(__half2*)&ra.x); a0 = fmaf(wa, p.x, a0); a1 = fmaf(wa, p.y, a1);
            p = __half22float2(*(__half2*)&ra.y); a2 = fmaf(wa, p.x, a2); a3 = fmaf(wa, p.y, a3);
            p = __half22float2(*(__half2*)&ra.z); a4 = fmaf(wa, p.x, a4); a5 = fmaf(wa, p.y, a5);
            p = __half22float2(*(__half2*)&ra.w); a6 = fmaf(wa, p.x, a6); a7 = fmaf(wa, p.y, a7);
            p = __half22float2(*(__half2*)&rb.x); a0 = fmaf(wb, p.x, a0); a1 = fmaf(wb, p.y, a1);
            p = __half22float2(*(__half2*)&rb.y); a2 = fmaf(wb, p.x, a2); a3 = fmaf(wb, p.y, a3);
            p = __half22float2(*(__half2*)&rb.z); a4 = fmaf(wb, p.x, a4); a5 = fmaf(wb, p.y, a5);
            p = __half22float2(*(__half2*)&rb.w); a6 = fmaf(wb, p.x, a6); a7 = fmaf(wb, p.y, a7);
        }
        for (; j < deg; j += 8) {
            int na = snbr[j];
            float wa = wrow[j];
            uint4 ra = *(const uint4*)(g_Wh1h + (size_t)na * F1 + q * 8);
            float2 p;
            p = __half22float2(*(__half2*)&ra.x); a0 = fmaf(wa, p.x, a0); a1 = fmaf(wa, p.y, a1);
            p = __half22float2(*(__half2*)&ra.y); a2 = fmaf(wa, p.x, a2); a3 = fmaf(wa, p.y, a3);
            p = __half22float2(*(__half2*)&ra.z); a4 = fmaf(wa, p.x, a4); a5 = fmaf(wa, p.y, a5);
            p = __half22float2(*(__half2*)&ra.w); a6 = fmaf(wa, p.x, a6); a7 = fmaf(wa, p.y, a7);
        }
        float* dstp = &sred[grp][q * 8];
        dstp[0]=a0; dstp[1]=a1; dstp[2]=a2; dstp[3]=a3;
        dstp[4]=a4; dstp[5]=a5; dstp[6]=a6; dstp[7]=a7;
    }
    __syncthreads();
    {   // combine partials + ELU -> sx (tid = col)
        float v = sred[0][tid] + sred[1][tid] + sred[2][tid] + sred[3][tid]
                + sred[4][tid] + sred[5][tid] + sred[6][tid] + sred[7][tid];
        sx[tid] = v > 0.f ? v : (__expf(v) - 1.f);
    }
    __syncthreads();
    // fused gemm2: Wh2[i] = sx @ W2 (128x64), split-k
    {
        const int q = tid & 15;    // col quad
        const int c = tid >> 4;    // k chunk
        float4 a = {0.f, 0.f, 0.f, 0.f};
        const float4* Wq = (const float4*)W2;
        #pragma unroll
        for (int kk = 0; kk < 16; kk++) {
            int k = c * 16 + kk;
            float4 w4 = Wq[k * 16 + q];
            float xv = sx[k];
            a.x = fmaf(xv, w4.x, a.x); a.y = fmaf(xv, w4.y, a.y);
            a.z = fmaf(xv, w4.z, a.z); a.w = fmaf(xv, w4.w, a.w);
        }
        spart[c][q] = a;
    }
    __syncthreads();
    if (tid < 16) {
        float4 r = {0.f, 0.f, 0.f, 0.f};
        #pragma unroll
        for (int c = 0; c < 8; c++) {
            float4 p = spart[c][tid];
            r.x += p.x; r.y += p.y; r.z += p.z; r.w += p.w;
        }
        __half2* dst = (__half2*)(g_Wh2h + (size_t)i * OUTD);
        dst[tid * 2]     = __floats2half2_rn(r.x, r.y);
        dst[tid * 2 + 1] = __floats2half2_rn(r.z, r.w);
        const float4 as = ((const float4*)a2s)[tid];
        const float4 ad = ((const float4*)a2d)[tid];
        float ps = r.x * as.x + r.y * as.y + r.z * as.z + r.w * as.w;
        float pd = r.x * ad.x + r.y * ad.y + r.z * ad.z + r.w * ad.w;
        #pragma unroll
        for (int d = 8; d; d >>= 1) {
            ps += __shfl_xor_sync(0xffffu, ps, d);
            pd += __shfl_xor_sync(0xffffu, pd, d);
        }
        if (tid == 0) { g_s2src[i] = ps; g_s2dst[i] = pd; }
    }
}

// ---------------- 3) layer-2 sparse softmax-aggregate -> out ----------------
__global__ __launch_bounds__(64) void agg2(float* __restrict__ out) {
    const int i = blockIdx.x;
    const int tid = threadIdx.x;     // 64
    const int wp = tid >> 5, lane = tid & 31;
    __shared__ int   snbr[CAP];
    __shared__ float sw[CAP];
    __shared__ float sred[8][OUTD];  // 2 KB
    __shared__ int   sdeg;
    if (tid == 0) sdeg = g_deg[i];
    __syncthreads();
    const int deg = sdeg;
    for (int t = tid; t < deg; t += 64) snbr[t] = g_nbr[i * CAP + t];
    __syncthreads();
    const float ssrc = g_s2src[i];
    for (int t = tid; t < deg; t += 64) {
        float e = ssrc + g_s2dst[snbr[t]];
        sw[t] = e > 0.f ? e : NEG_SLOPE * e;
    }
    __syncthreads();
    if (tid < 32) {
        float m = -1e30f;
        for (int j = tid; j < deg; j += 32) m = fmaxf(m, sw[j]);
        #pragma unroll
        for (int d = 16; d; d >>= 1) m = fmaxf(m, __shfl_xor_sync(0xffffffffu, m, d));
        float s = 0.f;
        for (int j = tid; j < deg; j += 32) s += __expf(sw[j] - m);
        #pragma unroll
        for (int d = 16; d; d >>= 1) s += __shfl_xor_sync(0xffffffffu, s, d);
        const float rinv = 1.f / s;
        for (int j = tid; j < deg; j += 32) sw[j] = __expf(sw[j] - m) * rinv;
    }
    __syncthreads();
    // gather fp16 Wh2 with LDG.128: 8 lanes/row, 4 rows per warp in flight
    {
        const int sub = lane >> 3;        // row-group within warp 0..3
        const int q = lane & 7;           // uint4 index within row (8 halfs)
        const int grp = wp * 4 + sub;     // 0..7
        float a0=0.f,a1=0.f,a2=0.f,a3=0.f,a4=0.f,a5=0.f,a6=0.f,a7=0.f;
        int j = grp;
        for (; j + 8 < deg; j += 16) {
            int na = snbr[j], nb = snbr[j + 8];
            float wa = sw[j], wb = sw[j + 8];
            uint4 ra = *(const uint4*)(g_Wh2h + (size_t)na * OUTD + q * 8);
            uint4 rb = *(const uint4*)(g_Wh2h + (size_t)nb * OUTD + q * 8);
            float2 p;
            p = __half22float2(*(__half2*)&ra.x); a0 = fmaf(wa, p.x, a0); a1 = fmaf(wa, p.y, a1);
            p = __half22float2(*(__half2*)&ra.y); a2 = fmaf(wa, p.x, a2); a3 = fmaf(wa, p.y, a3);
            p = __half22float2(*(__half2*)&ra.z); a4 = fmaf(wa, p.x, a4); a5 = fmaf(wa, p.y, a5);
            p = __half22float2(*(__half2*)&ra.w); a6 = fmaf(wa, p.x, a6); a7 = fmaf(wa, p.y, a7);
            p = __half22float2(*(__half2*)&rb.x); a0 = fmaf(wb, p.x, a0); a1 = fmaf(wb, p.y, a1);
            p = __half22float2(*(__half2*)&rb.y); a2 = fmaf(wb, p.x, a2); a3 = fmaf(wb, p.y, a3);
            p = __half22float2(*(__half2*)&rb.z); a4 = fmaf(wb, p.x, a4); a5 = fmaf(wb, p.y, a5);
            p = __half22float2(*(__half2*)&rb.w); a6 = fmaf(wb, p.x, a6); a7 = fmaf(wb, p.y, a7);
        }
        for (; j < deg; j += 8) {
            int na = snbr[j];
            float wa = sw[j];
            uint4 ra = *(const uint4*)(g_Wh2h + (size_t)na * OUTD + q * 8);
            float2 p;
            p = __half22float2(*(__half2*)&ra.x); a0 = fmaf(wa, p.x, a0); a1 = fmaf(wa, p.y, a1);
            p = __half22float2(*(__half2*)&ra.y); a2 = fmaf(wa, p.x, a2); a3 = fmaf(wa, p.y, a3);
            p = __half22float2(*(__half2*)&ra.z); a4 = fmaf(wa, p.x, a4); a5 = fmaf(wa, p.y, a5);
            p = __half22float2(*(__half2*)&ra.w); a6 = fmaf(wa, p.x, a6); a7 = fmaf(wa, p.y, a7);
        }
        float* dstp = &sred[grp][q * 8];
        dstp[0]=a0; dstp[1]=a1; dstp[2]=a2; dstp[3]=a3;
        dstp[4]=a4; dstp[5]=a5; dstp[6]=a6; dstp[7]=a7;
    }
    __syncthreads();
    {   // combine partials (tid = col)
        float v = sred[0][tid] + sred[1][tid] + sred[2][tid] + sred[3][tid]
                + sred[4][tid] + sred[5][tid] + sred[6][tid] + sred[7][tid];
        out[(size_t)i * OUTD + tid] = v;
    }
}

// ---------------- launcher ----------------
extern "C" void kernel_launch(void* const* d_in, const int* in_sizes, int n_in,
                              void* d_out, int out_size) {
    const float* adj = (const float*)d_in[0];
    const float* h   = (const float*)d_in[1];
    const float* W1  = (const float*)d_in[2];
    const float* a1s = (const float*)d_in[3];
    const float* a1d = (const float*)d_in[4];
    const float* W2  = (const float*)d_in[5];
    const float* a2s = (const float*)d_in[6];
    const float* a2d = (const float*)d_in[7];
    float* out = (float*)d_out;

    build_and_gemm1<<<1250, 256>>>(adj, h, W1, a1s, a1d);
    agg1_gemm2<<<NN, 128>>>(W2, a2s, a2d);
    agg2<<<NN, 64>>>(out);
}

// round 5
// speedup vs baseline: 2.1499x; 1.0210x over previous
#include <cuda_runtime.h>
#include <cuda_fp16.h>

#define NN 5000
#define IN_DIM 64
#define HID 32
#define NH 4
#define F1 (NH*HID)   // 128
#define OUTD 64
#define CAP 320
#define SWP 321       // padded stride (no 4-way bank conflict)
#define NEG_SLOPE 0.2f

// ---------------- device scratch ----------------
__device__ int   g_deg[NN];
__device__ int   g_nbr[NN * CAP];
__device__ __align__(16) __half g_Wh1h[NN * F1];   // fp16 for gather
__device__ float g_s1src[NN * NH];
__device__ float g_s1dst[NN * NH];
__device__ __align__(16) __half g_Wh2h[NN * OUTD]; // fp16 for gather
__device__ float g_s2src[NN];
__device__ float g_s2dst[NN];

// ---------------- 1) fused: build neighbor lists + gemm1 ----------------
// blocks [0,625): build (8 rows/block, 1 warp/row, 8 floats/lane/iter).
// blocks [625,1250): gemm1 (8 nodes/block).
__global__ __launch_bounds__(256) void build_and_gemm1(
        const float* __restrict__ adj, const float* __restrict__ h,
        const float* __restrict__ W1,
        const float* __restrict__ a1s, const float* __restrict__ a1d) {
    const int tid = threadIdx.x;
    if (blockIdx.x < 625) {
        // ---- build_nbr: 20 iterations of 256 cols (19 full + tail of 136) ----
        const int row = blockIdx.x * 8 + (tid >> 5);
        const int lane = tid & 31;
        const float* __restrict__ r = adj + (size_t)row * NN;
        int base = 0;
        float4 va = __ldcs((const float4*)(r + lane * 8));
        float4 vb = __ldcs((const float4*)(r + lane * 8 + 4));
        for (int it = 0; it < 20; it++) {
            // prefetch next iteration (iter 19 covers cols 4864..4999 -> lanes < 17)
            float4 na = make_float4(0.f, 0.f, 0.f, 0.f), nb = na;
            if (it < 18 || (it == 18 && lane < 17)) {
                const float* p = r + (it + 1) * 256 + lane * 8;
                na = __ldcs((const float4*)p);
                nb = __ldcs((const float4*)(p + 4));
            }
            unsigned m =
                  (__float_as_uint(va.x) ? 1u   : 0u)
                | (__float_as_uint(va.y) ? 2u   : 0u)
                | (__float_as_uint(va.z) ? 4u   : 0u)
                | (__float_as_uint(va.w) ? 8u   : 0u)
                | (__float_as_uint(vb.x) ? 16u  : 0u)
                | (__float_as_uint(vb.y) ? 32u  : 0u)
                | (__float_as_uint(vb.z) ? 64u  : 0u)
                | (__float_as_uint(vb.w) ? 128u : 0u);
            int cnt = __popc(m);
            int pref = cnt;
            #pragma unroll
            for (int d = 1; d < 32; d <<= 1) {
                int t = __shfl_up_sync(0xffffffffu, pref, d);
                if (lane >= d) pref += t;
            }
            int total = __shfl_sync(0xffffffffu, pref, 31);
            int o = base + (pref - cnt);
            int col = it * 256 + lane * 8;
            while (m) {                       // ~0.16 expected iters/lane
                int b = __ffs(m) - 1;
                m &= m - 1;
                if (o < CAP) g_nbr[row * CAP + o] = col + b;
                o++;
            }
            base += total;
            va = na; vb = nb;
        }
        if (lane == 0) g_deg[row] = base < CAP ? base : CAP;
    } else {
        // ---- gemm1: Wh1 = h @ W1, fused s1 scores, fp16 out ----
        __shared__ float sW[IN_DIM * F1];   // 32 KB
        __shared__ float shh[8 * IN_DIM];   // 2 KB
        const int node0 = (blockIdx.x - 625) * 8;
        #pragma unroll
        for (int i = 0; i < 8; i++)
            ((float4*)sW)[tid + i * 256] = ((const float4*)W1)[tid + i * 256];
        if (tid < 128)
            ((float4*)shh)[tid] = ((const float4*)(h + (size_t)node0 * IN_DIM))[tid];
        __syncthreads();
        const int tx = tid & 31;   // col quad
        const int ty = tid >> 5;   // node within tile
        const int node = node0 + ty;
        float4 acc = {0.f, 0.f, 0.f, 0.f};
        const float4* Wq = (const float4*)sW;
        #pragma unroll 16
        for (int k = 0; k < IN_DIM; k++) {
            float4 w = Wq[k * 32 + tx];
            float hv = shh[ty * IN_DIM + k];
            acc.x = fmaf(hv, w.x, acc.x); acc.y = fmaf(hv, w.y, acc.y);
            acc.z = fmaf(hv, w.z, acc.z); acc.w = fmaf(hv, w.w, acc.w);
        }
        __half2* dst = (__half2*)(g_Wh1h + (size_t)node * F1);
        dst[tx * 2]     = __floats2half2_rn(acc.x, acc.y);
        dst[tx * 2 + 1] = __floats2half2_rn(acc.z, acc.w);
        const float4 as = ((const float4*)a1s)[tx];
        const float4 ad = ((const float4*)a1d)[tx];
        float ps = acc.x * as.x + acc.y * as.y + acc.z * as.z + acc.w * as.w;
        float pd = acc.x * ad.x + acc.y * ad.y + acc.z * ad.z + acc.w * ad.w;
        #pragma unroll
        for (int d = 4; d; d >>= 1) {
            ps += __shfl_xor_sync(0xffffffffu, ps, d);
            pd += __shfl_xor_sync(0xffffffffu, pd, d);
        }
        if ((tx & 7) == 0) {
            g_s1src[node * NH + (tx >> 3)] = ps;
            g_s1dst[node * NH + (tx >> 3)] = pd;
        }
    }
}

// ---------------- 2) fused: layer-1 agg + ELU + x@W2 + s2 scores ----------
__global__ __launch_bounds__(128) void agg1_gemm2(
        const float* __restrict__ W2,
        const float* __restrict__ a2s, const float* __restrict__ a2d) {
    const int i = blockIdx.x;
    const int tid = threadIdx.x;     // 128
    const int w = tid >> 5, lane = tid & 31;
    __shared__ int    snbr[CAP];
    __shared__ float  swt[NH * SWP];
    __shared__ float  sred[8][F1];   // gather partials (4 KB)
    __shared__ float  sx[F1];        // ELU'd x row
    __shared__ float4 spart[8][16];  // split-k partials for x@W2
    __shared__ int    sdeg;
    if (tid == 0) sdeg = g_deg[i];
    __syncthreads();
    const int deg = sdeg;
    for (int t = tid; t < deg; t += 128) snbr[t] = g_nbr[i * CAP + t];
    __syncthreads();
    // scores: warp w owns head w
    {
        const float ssrc = g_s1src[i * NH + w];
        for (int j = lane; j < deg; j += 32) {
            float e = ssrc + g_s1dst[snbr[j] * NH + w];
            swt[w * SWP + j] = e > 0.f ? e : NEG_SLOPE * e;
        }
    }
    __syncthreads();
    {   // softmax: warp w owns head w
        float m = -1e30f;
        for (int j = lane; j < deg; j += 32) m = fmaxf(m, swt[w * SWP + j]);
        #pragma unroll
        for (int d = 16; d; d >>= 1) m = fmaxf(m, __shfl_xor_sync(0xffffffffu, m, d));
        float s = 0.f;
        for (int j = lane; j < deg; j += 32) s += __expf(swt[w * SWP + j] - m);
        #pragma unroll
        for (int d = 16; d; d >>= 1) s += __shfl_xor_sync(0xffffffffu, s, d);
        const float rinv = 1.f / s;
        for (int j = lane; j < deg; j += 32) swt[w * SWP + j] = __expf(swt[w * SWP + j] - m) * rinv;
    }
    __syncthreads();
    // gather fp16 Wh1 with LDG.128: 16 lanes/row, 2 rows per warp in flight
    {
        const int half = lane >> 4;
        const int q = lane & 15;             // uint4 index (8 halfs)
        const int head = q >> 2;
        const int grp = w * 2 + half;        // 0..7
        const float* __restrict__ wrow = swt + head * SWP;
        float a0=0.f,a1=0.f,a2=0.f,a3=0.f,a4=0.f,a5=0.f,a6=0.f,a7=0.f;
        int j = grp;
        for (; j + 8 < deg; j += 16) {
            int na = snbr[j], nb = snbr[j + 8];
            float wa = wrow[j], wb = wrow[j + 8];
            uint4 ra = *(const uint4*)(g_Wh1h + (size_t)na * F1 + q * 8);
            uint4 rb = *(const uint4*)(g_Wh1h + (size_t)nb * F1 + q * 8);
            float2 p;
            p = __half22float2(*(__half2*)&ra.x); a0 = fmaf(wa, p.x, a0); a1 = fmaf(wa, p.y, a1);
            p = __half22float2(*(__half2*)&ra.y); a2 = fmaf(wa, p.x, a2); a3 = fmaf(wa, p.y, a3);
            p = __half22float2(*(__half2*)&ra.z); a4 = fmaf(wa, p.x, a4); a5 = fmaf(wa, p.y, a5);
            p = __half22float2(*(__half2*)&ra.w); a6 = fmaf(wa, p.x, a6); a7 = fmaf(wa, p.y, a7);
            p = __half22float2(*(__half2*)&rb.x); a0 = fmaf(wb, p.x, a0); a1 = fmaf(wb, p.y, a1);
            p = __half22float2(*(__half2*)&rb.y); a2 = fmaf(wb, p.x, a2); a3 = fmaf(wb, p.y, a3);
            p = __half22float2(*(__half2*)&rb.z); a4 = fmaf(wb, p.x, a4); a5 = fmaf(wb, p.y, a5);
            p = __half22float2(*(__half2*)&rb.w); a6 = fmaf(wb, p.x, a6); a7 = fmaf(wb, p.y, a7);
        }
        for (; j < deg; j += 8) {
            int na = snbr[j];
            float wa = wrow[j];
            uint4 ra = *(const uint4*)(g_Wh1h + (size_t)na * F1 + q * 8);
            float2 p;
            p = __half22float2(*(__half2*)&ra.x); a0 = fmaf(wa, p.x, a0); a1 = fmaf(wa, p.y, a1);
            p = __half22float2(*(__half2*)&ra.y); a2 = fmaf(wa, p.x, a2); a3 = fmaf(wa, p.y, a3);
            p = __half22float2(*(__half2*)&ra.z); a4 = fmaf(wa, p.x, a4); a5 = fmaf(wa, p.y, a5);
            p = __half22float2(*(__half2*)&ra.w); a6 = fmaf(wa, p.x, a6); a7 = fmaf(wa, p.y, a7);
        }
        float* dstp = &sred[grp][q * 8];
        dstp[0]=a0; dstp[1]=a1; dstp[2]=a2; dstp[3]=a3;
        dstp[4]=a4; dstp[5]=a5; dstp[6]=a6; dstp[7]=a7;
    }
    __syncthreads();
    {   // combine partials + ELU -> sx (tid = col)
        float v = sred[0][tid] + sred[1][tid] + sred[2][tid] + sred[3][tid]
                + sred[4][tid] + sred[5][tid] + sred[6][tid] + sred[7][tid];
        sx[tid] = v > 0.f ? v : (__expf(v) - 1.f);
    }
    __syncthreads();
    // fused gemm2: Wh2[i] = sx @ W2 (128x64), split-k
    {
        const int q = tid & 15;
        const int c = tid >> 4;
        float4 a = {0.f, 0.f, 0.f, 0.f};
        const float4* Wq = (const float4*)W2;
        #pragma unroll
        for (int kk = 0; kk < 16; kk++) {
            int k = c * 16 + kk;
            float4 w4 = Wq[k * 16 + q];
            float xv = sx[k];
            a.x = fmaf(xv, w4.x, a.x); a.y = fmaf(xv, w4.y, a.y);
            a.z = fmaf(xv, w4.z, a.z); a.w = fmaf(xv, w4.w, a.w);
        }
        spart[c][q] = a;
    }
    __syncthreads();
    if (tid < 16) {
        float4 r = {0.f, 0.f, 0.f, 0.f};
        #pragma unroll
        for (int c = 0; c < 8; c++) {
            float4 p = spart[c][tid];
            r.x += p.x; r.y += p.y; r.z += p.z; r.w += p.w;
        }
        __half2* dst = (__half2*)(g_Wh2h + (size_t)i * OUTD);
        dst[tid * 2]     = __floats2half2_rn(r.x, r.y);
        dst[tid * 2 + 1] = __floats2half2_rn(r.z, r.w);
        const float4 as = ((const float4*)a2s)[tid];
        const float4 ad = ((const float4*)a2d)[tid];
        float ps = r.x * as.x + r.y * as.y + r.z * as.z + r.w * as.w;
        float pd = r.x * ad.x + r.y * ad.y + r.z * ad.z + r.w * ad.w;
        #pragma unroll
        for (int d = 8; d; d >>= 1) {
            ps += __shfl_xor_sync(0xffffu, ps, d);
            pd += __shfl_xor_sync(0xffffu, pd, d);
        }
        if (tid == 0) { g_s2src[i] = ps; g_s2dst[i] = pd; }
    }
}

// ---------------- 3) layer-2 sparse softmax-aggregate -> out ----------------
__global__ __launch_bounds__(64) void agg2(float* __restrict__ out) {
    const int i = blockIdx.x;
    const int tid = threadIdx.x;     // 64
    const int wp = tid >> 5, lane = tid & 31;
    __shared__ int   snbr[CAP];
    __shared__ float sw[CAP];
    __shared__ float sred[8][OUTD];
    __shared__ int   sdeg;
    if (tid == 0) sdeg = g_deg[i];
    __syncthreads();
    const int deg = sdeg;
    for (int t = tid; t < deg; t += 64) snbr[t] = g_nbr[i * CAP + t];
    __syncthreads();
    const float ssrc = g_s2src[i];
    for (int t = tid; t < deg; t += 64) {
        float e = ssrc + g_s2dst[snbr[t]];
        sw[t] = e > 0.f ? e : NEG_SLOPE * e;
    }
    __syncthreads();
    if (tid < 32) {
        float m = -1e30f;
        for (int j = tid; j < deg; j += 32) m = fmaxf(m, sw[j]);
        #pragma unroll
        for (int d = 16; d; d >>= 1) m = fmaxf(m, __shfl_xor_sync(0xffffffffu, m, d));
        float s = 0.f;
        for (int j = tid; j < deg; j += 32) s += __expf(sw[j] - m);
        #pragma unroll
        for (int d = 16; d; d >>= 1) s += __shfl_xor_sync(0xffffffffu, s, d);
        const float rinv = 1.f / s;
        for (int j = tid; j < deg; j += 32) sw[j] = __expf(sw[j] - m) * rinv;
    }
    __syncthreads();
    // gather fp16 Wh2 with LDG.128: 8 lanes/row, 4 rows per warp in flight
    {
        const int sub = lane >> 3;
        const int q = lane & 7;
        const int grp = wp * 4 + sub;     // 0..7
        float a0=0.f,a1=0.f,a2=0.f,a3=0.f,a4=0.f,a5=0.f,a6=0.f,a7=0.f;
        int j = grp;
        for (; j + 8 < deg; j += 16) {
            int na = snbr[j], nb = snbr[j + 8];
            float wa = sw[j], wb = sw[j + 8];
            uint4 ra = *(const uint4*)(g_Wh2h + (size_t)na * OUTD + q * 8);
            uint4 rb = *(const uint4*)(g_Wh2h + (size_t)nb * OUTD + q * 8);
            float2 p;
            p = __half22float2(*(__half2*)&ra.x); a0 = fmaf(wa, p.x, a0); a1 = fmaf(wa, p.y, a1);
            p = __half22float2(*(__half2*)&ra.y); a2 = fmaf(wa, p.x, a2); a3 = fmaf(wa, p.y, a3);
            p = __half22float2(*(__half2*)&ra.z); a4 = fmaf(wa, p.x, a4); a5 = fmaf(wa, p.y, a5);
            p = __half22float2(*(__half2*)&ra.w); a6 = fmaf(wa, p.x, a6); a7 = fmaf(wa, p.y, a7);
            p = __half22float2(*(__half2*)&rb.x); a0 = fmaf(wb, p.x, a0); a1 = fmaf(wb, p.y, a1);
            p = __half22float2(*(__half2*)&rb.y); a2 = fmaf(wb, p.x, a2); a3 = fmaf(wb, p.y, a3);
            p = __half22float2(*(__half2*)&rb.z); a4 = fmaf(wb, p.x, a4); a5 = fmaf(wb, p.y, a5);
            p = __half22float2(*(__half2*)&rb.w); a6 = fmaf(wb, p.x, a6); a7 = fmaf(wb, p.y, a7);
        }
        for (; j < deg; j += 8) {
            int na = snbr[j];
            float wa = sw[j];
            uint4 ra = *(const uint4*)(g_Wh2h + (size_t)na * OUTD + q * 8);
            float2 p;
            p = __half22float2(*(__half2*)&ra.x); a0 = fmaf(wa, p.x, a0); a1 = fmaf(wa, p.y, a1);
            p = __half22float2(*(__half2*)&ra.y); a2 = fmaf(wa, p.x, a2); a3 = fmaf(wa, p.y, a3);
            p = __half22float2(*(__half2*)&ra.z); a4 = fmaf(wa, p.x, a4); a5 = fmaf(wa, p.y, a5);
            p = __half22float2(*(__half2*)&ra.w); a6 = fmaf(wa, p.x, a6); a7 = fmaf(wa, p.y, a7);
        }
        float* dstp = &sred[grp][q * 8];
        dstp[0]=a0; dstp[1]=a1; dstp[2]=a2; dstp[3]=a3;
        dstp[4]=a4; dstp[5]=a5; dstp[6]=a6; dstp[7]=a7;
    }
    __syncthreads();
    {
        float v = sred[0][tid] + sred[1][tid] + sred[2][tid] + sred[3][tid]
                + sred[4][tid] + sred[5][tid] + sred[6][tid] + sred[7][tid];
        out[(size_t)i * OUTD + tid] = v;
    }
}

// ---------------- launcher ----------------
extern "C" void kernel_launch(void* const* d_in, const int* in_sizes, int n_in,
                              void* d_out, int out_size) {
    const float* adj = (const float*)d_in[0];
    const float* h   = (const float*)d_in[1];
    const float* W1  = (const float*)d_in[2];
    const float* a1s = (const float*)d_in[3];
    const float* a1d = (const float*)d_in[4];
    const float* W2  = (const float*)d_in[5];
    const float* a2s = (const float*)d_in[6];
    const float* a2d = (const float*)d_in[7];
    float* out = (float*)d_out;

    build_and_gemm1<<<1250, 256>>>(adj, h, W1, a1s, a1d);
    agg1_gemm2<<<NN, 128>>>(W2, a2s, a2d);
    agg2<<<NN, 64>>>(out);
}

// round 6
// speedup vs baseline: 2.2185x; 1.0319x over previous
#include <cuda_runtime.h>
#include <cuda_fp16.h>

#define NN 5000
#define IN_DIM 64
#define HID 32
#define NH 4
#define F1 (NH*HID)   // 128
#define OUTD 64
#define CAP 320
#define SWP 321       // padded stride (no 4-way bank conflict)
#define NEG_SLOPE 0.2f
#define LSLOT 20      // per-lane staging slots (P(overflow) ~ 1e-8)

// ---------------- device scratch ----------------
__device__ int   g_deg[NN];
__device__ int   g_nbr[NN * CAP];
__device__ __align__(16) __half g_Wh1h[NN * F1];   // fp16 for gather
__device__ float g_s1src[NN * NH];
__device__ float g_s1dst[NN * NH];
__device__ __align__(16) __half g_Wh2h[NN * OUTD]; // fp16 for gather
__device__ float g_s2src[NN];
__device__ float g_s2dst[NN];

// ---------------- 1) fused: build neighbor lists + gemm1 ----------------
// blocks [0,625): build (8 rows/block, 1 warp/row, lane-private staging,
//                 ONE prefix scan per row). order = fixed deterministic interleave.
// blocks [625,1250): gemm1 (8 nodes/block).
__global__ __launch_bounds__(256) void build_and_gemm1(
        const float* __restrict__ adj, const float* __restrict__ h,
        const float* __restrict__ W1,
        const float* __restrict__ a1s, const float* __restrict__ a1d) {
    __shared__ __align__(16) char sbuf[34816];   // union: build 10.2KB / gemm 34KB
    const int tid = threadIdx.x;
    if (blockIdx.x < 625) {
        // ---- build_nbr ----
        const int wi = tid >> 5, lane = tid & 31;
        const int row = blockIdx.x * 8 + wi;
        const float4* __restrict__ r4 = (const float4*)(adj + (size_t)row * NN);
        unsigned short* buf = (unsigned short*)sbuf + (wi * 32 + lane) * LSLOT;
        int cnt = 0;
        // 1250 float4 per row; lane owns f = it*32 + lane. 39 full iters, tail lanes 0,1.
        #pragma unroll 4
        for (int it = 0; it < 39; it++) {
            const int f = it * 32 + lane;
            float4 v = __ldcs(r4 + f);
            unsigned m = (__float_as_uint(v.x) ? 1u : 0u)
                       | (__float_as_uint(v.y) ? 2u : 0u)
                       | (__float_as_uint(v.z) ? 4u : 0u)
                       | (__float_as_uint(v.w) ? 8u : 0u);
            const int colb = f * 4;
            while (m) {
                int b = __ffs(m) - 1;
                m &= m - 1;
                if (cnt < LSLOT) buf[cnt] = (unsigned short)(colb + b);
                cnt++;
            }
        }
        if (lane < 2) {   // f = 1248, 1249
            const int f = 1248 + lane;
            float4 v = __ldcs(r4 + f);
            unsigned m = (__float_as_uint(v.x) ? 1u : 0u)
                       | (__float_as_uint(v.y) ? 2u : 0u)
                       | (__float_as_uint(v.z) ? 4u : 0u)
                       | (__float_as_uint(v.w) ? 8u : 0u);
            const int colb = f * 4;
            while (m) {
                int b = __ffs(m) - 1;
                m &= m - 1;
                if (cnt < LSLOT) buf[cnt] = (unsigned short)(colb + b);
                cnt++;
            }
        }
        cnt = cnt < LSLOT ? cnt : LSLOT;
        // ONE prefix scan per row
        int pref = cnt;
        #pragma unroll
        for (int d = 1; d < 32; d <<= 1) {
            int t = __shfl_up_sync(0xffffffffu, pref, d);
            if (lane >= d) pref += t;
        }
        const int total = __shfl_sync(0xffffffffu, pref, 31);
        int off = pref - cnt;
        for (int k = 0; k < cnt; k++) {
            int o = off + k;
            if (o < CAP) g_nbr[row * CAP + o] = buf[k];
        }
        if (lane == 0) g_deg[row] = total < CAP ? total : CAP;
    } else {
        // ---- gemm1: Wh1 = h @ W1, fused s1 scores, fp16 out ----
        float* sW = (float*)sbuf;                 // 32 KB
        float* shh = (float*)(sbuf + 32768);      // 2 KB
        const int node0 = (blockIdx.x - 625) * 8;
        #pragma unroll
        for (int i = 0; i < 8; i++)
            ((float4*)sW)[tid + i * 256] = ((const float4*)W1)[tid + i * 256];
        if (tid < 128)
            ((float4*)shh)[tid] = ((const float4*)(h + (size_t)node0 * IN_DIM))[tid];
        __syncthreads();
        const int tx = tid & 31;   // col quad
        const int ty = tid >> 5;   // node within tile
        const int node = node0 + ty;
        float4 acc = {0.f, 0.f, 0.f, 0.f};
        const float4* Wq = (const float4*)sW;
        #pragma unroll 16
        for (int k = 0; k < IN_DIM; k++) {
            float4 w = Wq[k * 32 + tx];
            float hv = shh[ty * IN_DIM + k];
            acc.x = fmaf(hv, w.x, acc.x); acc.y = fmaf(hv, w.y, acc.y);
            acc.z = fmaf(hv, w.z, acc.z); acc.w = fmaf(hv, w.w, acc.w);
        }
        __half2* dst = (__half2*)(g_Wh1h + (size_t)node * F1);
        dst[tx * 2]     = __floats2half2_rn(acc.x, acc.y);
        dst[tx * 2 + 1] = __floats2half2_rn(acc.z, acc.w);
        const float4 as = ((const float4*)a1s)[tx];
        const float4 ad = ((const float4*)a1d)[tx];
        float ps = acc.x * as.x + acc.y * as.y + acc.z * as.z + acc.w * as.w;
        float pd = acc.x * ad.x + acc.y * ad.y + acc.z * ad.z + acc.w * ad.w;
        #pragma unroll
        for (int d = 4; d; d >>= 1) {
            ps += __shfl_xor_sync(0xffffffffu, ps, d);
            pd += __shfl_xor_sync(0xffffffffu, pd, d);
        }
        if ((tx & 7) == 0) {
            g_s1src[node * NH + (tx >> 3)] = ps;
            g_s1dst[node * NH + (tx >> 3)] = pd;
        }
    }
}

// ---------------- 2) fused: layer-1 agg + ELU + x@W2 + s2 scores ----------
__global__ __launch_bounds__(128) void agg1_gemm2(
        const float* __restrict__ W2,
        const float* __restrict__ a2s, const float* __restrict__ a2d) {
    const int i = blockIdx.x;
    const int tid = threadIdx.x;     // 128
    const int w = tid >> 5, lane = tid & 31;
    __shared__ int    snbr[CAP];
    __shared__ float  swt[NH * SWP];
    __shared__ float  sred[8][F1];   // gather partials (4 KB)
    __shared__ float  sx[F1];        // ELU'd x row
    __shared__ float4 spart[8][16];  // split-k partials for x@W2
    __shared__ int    sdeg;
    if (tid == 0) sdeg = g_deg[i];
    __syncthreads();
    const int deg = sdeg;
    for (int t = tid; t < deg; t += 128) snbr[t] = g_nbr[i * CAP + t];
    __syncthreads();
    // scores: warp w owns head w
    {
        const float ssrc = g_s1src[i * NH + w];
        for (int j = lane; j < deg; j += 32) {
            float e = ssrc + g_s1dst[snbr[j] * NH + w];
            swt[w * SWP + j] = e > 0.f ? e : NEG_SLOPE * e;
        }
    }
    __syncthreads();
    {   // softmax: warp w owns head w
        float m = -1e30f;
        for (int j = lane; j < deg; j += 32) m = fmaxf(m, swt[w * SWP + j]);
        #pragma unroll
        for (int d = 16; d; d >>= 1) m = fmaxf(m, __shfl_xor_sync(0xffffffffu, m, d));
        float s = 0.f;
        for (int j = lane; j < deg; j += 32) s += __expf(swt[w * SWP + j] - m);
        #pragma unroll
        for (int d = 16; d; d >>= 1) s += __shfl_xor_sync(0xffffffffu, s, d);
        const float rinv = 1.f / s;
        for (int j = lane; j < deg; j += 32) swt[w * SWP + j] = __expf(swt[w * SWP + j] - m) * rinv;
    }
    __syncthreads();
    // gather fp16 Wh1 with LDG.128: 16 lanes/row, 2 rows per warp in flight
    {
        const int half = lane >> 4;
        const int q = lane & 15;             // uint4 index (8 halfs)
        const int head = q >> 2;
        const int grp = w * 2 + half;        // 0..7
        const float* __restrict__ wrow = swt + head * SWP;
        float a0=0.f,a1=0.f,a2=0.f,a3=0.f,a4=0.f,a5=0.f,a6=0.f,a7=0.f;
        int j = grp;
        for (; j + 8 < deg; j += 16) {
            int na = snbr[j], nb = snbr[j + 8];
            float wa = wrow[j], wb = wrow[j + 8];
            uint4 ra = *(const uint4*)(g_Wh1h + (size_t)na * F1 + q * 8);
            uint4 rb = *(const uint4*)(g_Wh1h + (size_t)nb * F1 + q * 8);
            float2 p;
            p = __half22float2(*(__half2*)&ra.x); a0 = fmaf(wa, p.x, a0); a1 = fmaf(wa, p.y, a1);
            p = __half22float2(*(__half2*)&ra.y); a2 = fmaf(wa, p.x, a2); a3 = fmaf(wa, p.y, a3);
            p = __half22float2(*(__half2*)&ra.z); a4 = fmaf(wa, p.x, a4); a5 = fmaf(wa, p.y, a5);
            p = __half22float2(*(__half2*)&ra.w); a6 = fmaf(wa, p.x, a6); a7 = fmaf(wa, p.y, a7);
            p = __half22float2(*(__half2*)&rb.x); a0 = fmaf(wb, p.x, a0); a1 = fmaf(wb, p.y, a1);
            p = __half22float2(*(__half2*)&rb.y); a2 = fmaf(wb, p.x, a2); a3 = fmaf(wb, p.y, a3);
            p = __half22float2(*(__half2*)&rb.z); a4 = fmaf(wb, p.x, a4); a5 = fmaf(wb, p.y, a5);
            p = __half22float2(*(__half2*)&rb.w); a6 = fmaf(wb, p.x, a6); a7 = fmaf(wb, p.y, a7);
        }
        for (; j < deg; j += 8) {
            int na = snbr[j];
            float wa = wrow[j];
            uint4 ra = *(const uint4*)(g_Wh1h + (size_t)na * F1 + q * 8);
            float2 p;
            p = __half22float2(*(__half2*)&ra.x); a0 = fmaf(wa, p.x, a0); a1 = fmaf(wa, p.y, a1);
            p = __half22float2(*(__half2*)&ra.y); a2 = fmaf(wa, p.x, a2); a3 = fmaf(wa, p.y, a3);
            p = __half22float2(*(__half2*)&ra.z); a4 = fmaf(wa, p.x, a4); a5 = fmaf(wa, p.y, a5);
            p = __half22float2(*(__half2*)&ra.w); a6 = fmaf(wa, p.x, a6); a7 = fmaf(wa, p.y, a7);
        }
        float* dstp = &sred[grp][q * 8];
        dstp[0]=a0; dstp[1]=a1; dstp[2]=a2; dstp[3]=a3;
        dstp[4]=a4; dstp[5]=a5; dstp[6]=a6; dstp[7]=a7;
    }
    __syncthreads();
    {   // combine partials + ELU -> sx (tid = col)
        float v = sred[0][tid] + sred[1][tid] + sred[2][tid] + sred[3][tid]
                + sred[4][tid] + sred[5][tid] + sred[6][tid] + sred[7][tid];
        sx[tid] = v > 0.f ? v : (__expf(v) - 1.f);
    }
    __syncthreads();
    // fused gemm2: Wh2[i] = sx @ W2 (128x64), split-k
    {
        const int q = tid & 15;
        const int c = tid >> 4;
        float4 a = {0.f, 0.f, 0.f, 0.f};
        const float4* Wq = (const float4*)W2;
        #pragma unroll
        for (int kk = 0; kk < 16; kk++) {
            int k = c * 16 + kk;
            float4 w4 = Wq[k * 16 + q];
            float xv = sx[k];
            a.x = fmaf(xv, w4.x, a.x); a.y = fmaf(xv, w4.y, a.y);
            a.z = fmaf(xv, w4.z, a.z); a.w = fmaf(xv, w4.w, a.w);
        }
        spart[c][q] = a;
    }
    __syncthreads();
    if (tid < 16) {
        float4 r = {0.f, 0.f, 0.f, 0.f};
        #pragma unroll
        for (int c = 0; c < 8; c++) {
            float4 p = spart[c][tid];
            r.x += p.x; r.y += p.y; r.z += p.z; r.w += p.w;
        }
        __half2* dst = (__half2*)(g_Wh2h + (size_t)i * OUTD);
        dst[tid * 2]     = __floats2half2_rn(r.x, r.y);
        dst[tid * 2 + 1] = __floats2half2_rn(r.z, r.w);
        const float4 as = ((const float4*)a2s)[tid];
        const float4 ad = ((const float4*)a2d)[tid];
        float ps = r.x * as.x + r.y * as.y + r.z * as.z + r.w * as.w;
        float pd = r.x * ad.x + r.y * ad.y + r.z * ad.z + r.w * ad.w;
        #pragma unroll
        for (int d = 8; d; d >>= 1) {
            ps += __shfl_xor_sync(0xffffu, ps, d);
            pd += __shfl_xor_sync(0xffffu, pd, d);
        }
        if (tid == 0) { g_s2src[i] = ps; g_s2dst[i] = pd; }
    }
}

// ---------------- 3) layer-2 sparse softmax-aggregate -> out ----------------
__global__ __launch_bounds__(64) void agg2(float* __restrict__ out) {
    const int i = blockIdx.x;
    const int tid = threadIdx.x;     // 64
    const int wp = tid >> 5, lane = tid & 31;
    __shared__ int   snbr[CAP];
    __shared__ float sw[CAP];
    __shared__ float sred[8][OUTD];
    __shared__ int   sdeg;
    if (tid == 0) sdeg = g_deg[i];
    __syncthreads();
    const int deg = sdeg;
    for (int t = tid; t < deg; t += 64) snbr[t] = g_nbr[i * CAP + t];
    __syncthreads();
    const float ssrc = g_s2src[i];
    for (int t = tid; t < deg; t += 64) {
        float e = ssrc + g_s2dst[snbr[t]];
        sw[t] = e > 0.f ? e : NEG_SLOPE * e;
    }
    __syncthreads();
    if (tid < 32) {
        float m = -1e30f;
        for (int j = tid; j < deg; j += 32) m = fmaxf(m, sw[j]);
        #pragma unroll
        for (int d = 16; d; d >>= 1) m = fmaxf(m, __shfl_xor_sync(0xffffffffu, m, d));
        float s = 0.f;
        for (int j = tid; j < deg; j += 32) s += __expf(sw[j] - m);
        #pragma unroll
        for (int d = 16; d; d >>= 1) s += __shfl_xor_sync(0xffffffffu, s, d);
        const float rinv = 1.f / s;
        for (int j = tid; j < deg; j += 32) sw[j] = __expf(sw[j] - m) * rinv;
    }
    __syncthreads();
    // gather fp16 Wh2 with LDG.128: 8 lanes/row, 4 rows per warp in flight
    {
        const int sub = lane >> 3;
        const int q = lane & 7;
        const int grp = wp * 4 + sub;     // 0..7
        float a0=0.f,a1=0.f,a2=0.f,a3=0.f,a4=0.f,a5=0.f,a6=0.f,a7=0.f;
        int j = grp;
        for (; j + 8 < deg; j += 16) {
            int na = snbr[j], nb = snbr[j + 8];
            float wa = sw[j], wb = sw[j + 8];
            uint4 ra = *(const uint4*)(g_Wh2h + (size_t)na * OUTD + q * 8);
            uint4 rb = *(const uint4*)(g_Wh2h + (size_t)nb * OUTD + q * 8);
            float2 p;
            p = __half22float2(*(__half2*)&ra.x); a0 = fmaf(wa, p.x, a0); a1 = fmaf(wa, p.y, a1);
            p = __half22float2(*(__half2*)&ra.y); a2 = fmaf(wa, p.x, a2); a3 = fmaf(wa, p.y, a3);
            p = __half22float2(*(__half2*)&ra.z); a4 = fmaf(wa, p.x, a4); a5 = fmaf(wa, p.y, a5);
            p = __half22float2(*(__half2*)&ra.w); a6 = fmaf(wa, p.x, a6); a7 = fmaf(wa, p.y, a7);
            p = __half22float2(*(__half2*)&rb.x); a0 = fmaf(wb, p.x, a0); a1 = fmaf(wb, p.y, a1);
            p = __half22float2(*(__half2*)&rb.y); a2 = fmaf(wb, p.x, a2); a3 = fmaf(wb, p.y, a3);
            p = __half22float2(*(__half2*)&rb.z); a4 = fmaf(wb, p.x, a4); a5 = fmaf(wb, p.y, a5);
            p = __half22float2(*(__half2*)&rb.w); a6 = fmaf(wb, p.x, a6); a7 = fmaf(wb, p.y, a7);
        }
        for (; j < deg; j += 8) {
            int na = snbr[j];
            float wa = sw[j];
            uint4 ra = *(const uint4*)(g_Wh2h + (size_t)na * OUTD + q * 8);
            float2 p;
            p = __half22float2(*(__half2*)&ra.x); a0 = fmaf(wa, p.x, a0); a1 = fmaf(wa, p.y, a1);
            p = __half22float2(*(__half2*)&ra.y); a2 = fmaf(wa, p.x, a2); a3 = fmaf(wa, p.y, a3);
            p = __half22float2(*(__half2*)&ra.z); a4 = fmaf(wa, p.x, a4); a5 = fmaf(wa, p.y, a5);
            p = __half22float2(*(__half2*)&ra.w); a6 = fmaf(wa, p.x, a6); a7 = fmaf(wa, p.y, a7);
        }
        float* dstp = &sred[grp][q * 8];
        dstp[0]=a0; dstp[1]=a1; dstp[2]=a2; dstp[3]=a3;
        dstp[4]=a4; dstp[5]=a5; dstp[6]=a6; dstp[7]=a7;
    }
    __syncthreads();
    {
        float v = sred[0][tid] + sred[1][tid] + sred[2][tid] + sred[3][tid]
                + sred[4][tid] + sred[5][tid] + sred[6][tid] + sred[7][tid];
        out[(size_t)i * OUTD + tid] = v;
    }
}

// ---------------- launcher ----------------
extern "C" void kernel_launch(void* const* d_in, const int* in_sizes, int n_in,
                              void* d_out, int out_size) {
    const float* adj = (const float*)d_in[0];
    const float* h   = (const float*)d_in[1];
    const float* W1  = (const float*)d_in[2];
    const float* a1s = (const float*)d_in[3];
    const float* a1d = (const float*)d_in[4];
    const float* W2  = (const float*)d_in[5];
    const float* a2s = (const float*)d_in[6];
    const float* a2d = (const float*)d_in[7];
    float* out = (float*)d_out;

    build_and_gemm1<<<1250, 256>>>(adj, h, W1, a1s, a1d);
    agg1_gemm2<<<NN, 128>>>(W2, a2s, a2d);
    agg2<<<NN, 64>>>(out);
}

// round 7
// speedup vs baseline: 2.5746x; 1.1605x over previous
#include <cuda_runtime.h>
#include <cuda_fp16.h>

#define NN 5000
#define IN_DIM 64
#define HID 32
#define NH 4
#define F1 (NH*HID)   // 128
#define OUTD 64
#define CAP 320
#define SWP 321       // padded stride (no 4-way bank conflict)
#define NEG_SLOPE 0.2f
#define LSLOT 20      // per-lane staging slots (P(overflow) ~ 1e-8)

// ---------------- device scratch ----------------
__device__ int   g_deg[NN];
__device__ int   g_nbr[NN * CAP];
__device__ __align__(16) __half g_Wh1h[NN * F1];   // fp16 for gather
__device__ float g_s1src[NN * NH];
__device__ float g_s1dst[NN * NH];
__device__ __align__(16) __half g_Wh2h[NN * OUTD]; // fp16 for gather
__device__ float g_s2src[NN];
__device__ float g_s2dst[NN];

// ---------------- 1) fused: build neighbor lists + gemm1 ----------------
// blocks [0,625): build (8 rows/block, 1 warp/row, lane-private staging,
//                 front-batched LDG.128 groups of 4, ONE prefix scan per row).
// blocks [625,1250): gemm1 (8 nodes/block, W1 via __ldg / L1).
__global__ __launch_bounds__(256, 8) void build_and_gemm1(
        const float* __restrict__ adj, const float* __restrict__ h,
        const float* __restrict__ W1,
        const float* __restrict__ a1s, const float* __restrict__ a1d) {
    __shared__ __align__(16) char sbuf[10240];   // union: build 10KB / gemm 2KB
    const int tid = threadIdx.x;
    if (blockIdx.x < 625) {
        // ---- build_nbr ----
        const int wi = tid >> 5, lane = tid & 31;
        const int row = blockIdx.x * 8 + wi;
        const float4* __restrict__ r4 = (const float4*)(adj + (size_t)row * NN);
        unsigned short* buf = (unsigned short*)sbuf + (wi * 32 + lane) * LSLOT;
        int cnt = 0;
        // lane owns f = it*32 + lane; 39 full iterations in groups of 4 (+3), then tail
        #define PROC(v, f) do { \
            unsigned m = (__float_as_uint((v).x) ? 1u : 0u) \
                       | (__float_as_uint((v).y) ? 2u : 0u) \
                       | (__float_as_uint((v).z) ? 4u : 0u) \
                       | (__float_as_uint((v).w) ? 8u : 0u); \
            const int colb = (f) * 4; \
            while (m) { \
                int b = __ffs(m) - 1; \
                m &= m - 1; \
                if (cnt < LSLOT) buf[cnt] = (unsigned short)(colb + b); \
                cnt++; \
            } } while (0)
        #pragma unroll 1
        for (int g = 0; g < 9; g++) {
            const int f0 = g * 128 + lane;
            float4 v0 = __ldcs(r4 + f0);
            float4 v1 = __ldcs(r4 + f0 + 32);
            float4 v2 = __ldcs(r4 + f0 + 64);
            float4 v3 = __ldcs(r4 + f0 + 96);
            PROC(v0, f0); PROC(v1, f0 + 32); PROC(v2, f0 + 64); PROC(v3, f0 + 96);
        }
        {   // iterations 36..38 (f up to 1247)
            const int f0 = 1152 + lane;
            float4 v0 = __ldcs(r4 + f0);
            float4 v1 = __ldcs(r4 + f0 + 32);
            float4 v2 = __ldcs(r4 + f0 + 64);
            PROC(v0, f0); PROC(v1, f0 + 32); PROC(v2, f0 + 64);
        }
        if (lane < 2) {   // f = 1248, 1249
            const int f = 1248 + lane;
            float4 v = __ldcs(r4 + f);
            PROC(v, f);
        }
        #undef PROC
        cnt = cnt < LSLOT ? cnt : LSLOT;
        // ONE prefix scan per row
        int pref = cnt;
        #pragma unroll
        for (int d = 1; d < 32; d <<= 1) {
            int t = __shfl_up_sync(0xffffffffu, pref, d);
            if (lane >= d) pref += t;
        }
        const int total = __shfl_sync(0xffffffffu, pref, 31);
        int off = pref - cnt;
        for (int k = 0; k < cnt; k++) {
            int o = off + k;
            if (o < CAP) g_nbr[row * CAP + o] = buf[k];
        }
        if (lane == 0) g_deg[row] = total < CAP ? total : CAP;
    } else {
        // ---- gemm1: Wh1 = h @ W1 (W1 via L1), fused s1 scores, fp16 out ----
        float* shh = (float*)sbuf;      // 2 KB
        const int node0 = (blockIdx.x - 625) * 8;
        if (tid < 128)
            ((float4*)shh)[tid] = ((const float4*)(h + (size_t)node0 * IN_DIM))[tid];
        __syncthreads();
        const int tx = tid & 31;   // col quad
        const int ty = tid >> 5;   // node within tile
        const int node = node0 + ty;
        float4 acc = {0.f, 0.f, 0.f, 0.f};
        const float4* __restrict__ Wq = (const float4*)W1;
        #pragma unroll 8
        for (int k = 0; k < IN_DIM; k++) {
            float4 w = __ldg(Wq + k * 32 + tx);
            float hv = shh[ty * IN_DIM + k];
            acc.x = fmaf(hv, w.x, acc.x); acc.y = fmaf(hv, w.y, acc.y);
            acc.z = fmaf(hv, w.z, acc.z); acc.w = fmaf(hv, w.w, acc.w);
        }
        __half2* dst = (__half2*)(g_Wh1h + (size_t)node * F1);
        dst[tx * 2]     = __floats2half2_rn(acc.x, acc.y);
        dst[tx * 2 + 1] = __floats2half2_rn(acc.z, acc.w);
        const float4 as = __ldg((const float4*)a1s + tx);
        const float4 ad = __ldg((const float4*)a1d + tx);
        float ps = acc.x * as.x + acc.y * as.y + acc.z * as.z + acc.w * as.w;
        float pd = acc.x * ad.x + acc.y * ad.y + acc.z * ad.z + acc.w * ad.w;
        #pragma unroll
        for (int d = 4; d; d >>= 1) {
            ps += __shfl_xor_sync(0xffffffffu, ps, d);
            pd += __shfl_xor_sync(0xffffffffu, pd, d);
        }
        if ((tx & 7) == 0) {
            g_s1src[node * NH + (tx >> 3)] = ps;
            g_s1dst[node * NH + (tx >> 3)] = pd;
        }
    }
}

// ---------------- 2) fused: layer-1 agg + ELU + x@W2 + s2 scores ----------
__global__ __launch_bounds__(128) void agg1_gemm2(
        const float* __restrict__ W2,
        const float* __restrict__ a2s, const float* __restrict__ a2d) {
    const int i = blockIdx.x;
    const int tid = threadIdx.x;     // 128
    const int w = tid >> 5, lane = tid & 31;
    __shared__ int    snbr[CAP];
    __shared__ float  swt[NH * SWP];
    __shared__ float  sred[8][F1];   // gather partials (4 KB)
    __shared__ float  sx[F1];        // ELU'd x row
    __shared__ float4 spart[8][16];  // split-k partials for x@W2
    __shared__ int    sdeg;
    if (tid == 0) sdeg = g_deg[i];
    __syncthreads();
    const int deg = sdeg;
    for (int t = tid; t < deg; t += 128) snbr[t] = g_nbr[i * CAP + t];
    __syncthreads();
    // scores: warp w owns head w
    {
        const float ssrc = g_s1src[i * NH + w];
        for (int j = lane; j < deg; j += 32) {
            float e = ssrc + g_s1dst[snbr[j] * NH + w];
            swt[w * SWP + j] = e > 0.f ? e : NEG_SLOPE * e;
        }
    }
    __syncthreads();
    {   // softmax: warp w owns head w
        float m = -1e30f;
        for (int j = lane; j < deg; j += 32) m = fmaxf(m, swt[w * SWP + j]);
        #pragma unroll
        for (int d = 16; d; d >>= 1) m = fmaxf(m, __shfl_xor_sync(0xffffffffu, m, d));
        float s = 0.f;
        for (int j = lane; j < deg; j += 32) s += __expf(swt[w * SWP + j] - m);
        #pragma unroll
        for (int d = 16; d; d >>= 1) s += __shfl_xor_sync(0xffffffffu, s, d);
        const float rinv = 1.f / s;
        for (int j = lane; j < deg; j += 32) swt[w * SWP + j] = __expf(swt[w * SWP + j] - m) * rinv;
    }
    __syncthreads();
    // gather fp16 Wh1 with LDG.128: 16 lanes/row, 2 rows per warp in flight
    {
        const int half = lane >> 4;
        const int q = lane & 15;             // uint4 index (8 halfs)
        const int head = q >> 2;
        const int grp = w * 2 + half;        // 0..7
        const float* __restrict__ wrow = swt + head * SWP;
        float a0=0.f,a1=0.f,a2=0.f,a3=0.f,a4=0.f,a5=0.f,a6=0.f,a7=0.f;
        int j = grp;
        for (; j + 8 < deg; j += 16) {
            int na = snbr[j], nb = snbr[j + 8];
            float wa = wrow[j], wb = wrow[j + 8];
            uint4 ra = *(const uint4*)(g_Wh1h + (size_t)na * F1 + q * 8);
            uint4 rb = *(const uint4*)(g_Wh1h + (size_t)nb * F1 + q * 8);
            float2 p;
            p = __half22float2(*(__half2*)&ra.x); a0 = fmaf(wa, p.x, a0); a1 = fmaf(wa, p.y, a1);
            p = __half22float2(*(__half2*)&ra.y); a2 = fmaf(wa, p.x, a2); a3 = fmaf(wa, p.y, a3);
            p = __half22float2(*(__half2*)&ra.z); a4 = fmaf(wa, p.x, a4); a5 = fmaf(wa, p.y, a5);
            p = __half22float2(*(__half2*)&ra.w); a6 = fmaf(wa, p.x, a6); a7 = fmaf(wa, p.y, a7);
            p = __half22float2(*(__half2*)&rb.x); a0 = fmaf(wb, p.x, a0); a1 = fmaf(wb, p.y, a1);
            p = __half22float2(*(__half2*)&rb.y); a2 = fmaf(wb, p.x, a2); a3 = fmaf(wb, p.y, a3);
            p = __half22float2(*(__half2*)&rb.z); a4 = fmaf(wb, p.x, a4); a5 = fmaf(wb, p.y, a5);
            p = __half22float2(*(__half2*)&rb.w); a6 = fmaf(wb, p.x, a6); a7 = fmaf(wb, p.y, a7);
        }
        for (; j < deg; j += 8) {
            int na = snbr[j];
            float wa = wrow[j];
            uint4 ra = *(const uint4*)(g_Wh1h + (size_t)na * F1 + q * 8);
            float2 p;
            p = __half22float2(*(__half2*)&ra.x); a0 = fmaf(wa, p.x, a0); a1 = fmaf(wa, p.y, a1);
            p = __half22float2(*(__half2*)&ra.y); a2 = fmaf(wa, p.x, a2); a3 = fmaf(wa, p.y, a3);
            p = __half22float2(*(__half2*)&ra.z); a4 = fmaf(wa, p.x, a4); a5 = fmaf(wa, p.y, a5);
            p = __half22float2(*(__half2*)&ra.w); a6 = fmaf(wa, p.x, a6); a7 = fmaf(wa, p.y, a7);
        }
        float* dstp = &sred[grp][q * 8];
        dstp[0]=a0; dstp[1]=a1; dstp[2]=a2; dstp[3]=a3;
        dstp[4]=a4; dstp[5]=a5; dstp[6]=a6; dstp[7]=a7;
    }
    __syncthreads();
    {   // combine partials + ELU -> sx (tid = col)
        float v = sred[0][tid] + sred[1][tid] + sred[2][tid] + sred[3][tid]
                + sred[4][tid] + sred[5][tid] + sred[6][tid] + sred[7][tid];
        sx[tid] = v > 0.f ? v : (__expf(v) - 1.f);
    }
    __syncthreads();
    // fused gemm2: Wh2[i] = sx @ W2 (128x64), split-k
    {
        const int q = tid & 15;
        const int c = tid >> 4;
        float4 a = {0.f, 0.f, 0.f, 0.f};
        const float4* Wq = (const float4*)W2;
        #pragma unroll
        for (int kk = 0; kk < 16; kk++) {
            int k = c * 16 + kk;
            float4 w4 = Wq[k * 16 + q];
            float xv = sx[k];
            a.x = fmaf(xv, w4.x, a.x); a.y = fmaf(xv, w4.y, a.y);
            a.z = fmaf(xv, w4.z, a.z); a.w = fmaf(xv, w4.w, a.w);
        }
        spart[c][q] = a;
    }
    __syncthreads();
    if (tid < 16) {
        float4 r = {0.f, 0.f, 0.f, 0.f};
        #pragma unroll
        for (int c = 0; c < 8; c++) {
            float4 p = spart[c][tid];
            r.x += p.x; r.y += p.y; r.z += p.z; r.w += p.w;
        }
        __half2* dst = (__half2*)(g_Wh2h + (size_t)i * OUTD);
        dst[tid * 2]     = __floats2half2_rn(r.x, r.y);
        dst[tid * 2 + 1] = __floats2half2_rn(r.z, r.w);
        const float4 as = ((const float4*)a2s)[tid];
        const float4 ad = ((const float4*)a2d)[tid];
        float ps = r.x * as.x + r.y * as.y + r.z * as.z + r.w * as.w;
        float pd = r.x * ad.x + r.y * ad.y + r.z * ad.z + r.w * ad.w;
        #pragma unroll
        for (int d = 8; d; d >>= 1) {
            ps += __shfl_xor_sync(0xffffu, ps, d);
            pd += __shfl_xor_sync(0xffffu, pd, d);
        }
        if (tid == 0) { g_s2src[i] = ps; g_s2dst[i] = pd; }
    }
}

// ---------------- 3) layer-2 sparse softmax-aggregate -> out ----------------
__global__ __launch_bounds__(64) void agg2(float* __restrict__ out) {
    const int i = blockIdx.x;
    const int tid = threadIdx.x;     // 64
    const int wp = tid >> 5, lane = tid & 31;
    __shared__ int   snbr[CAP];
    __shared__ float sw[CAP];
    __shared__ float sred[8][OUTD];
    __shared__ int   sdeg;
    if (tid == 0) sdeg = g_deg[i];
    __syncthreads();
    const int deg = sdeg;
    for (int t = tid; t < deg; t += 64) snbr[t] = g_nbr[i * CAP + t];
    __syncthreads();
    const float ssrc = g_s2src[i];
    for (int t = tid; t < deg; t += 64) {
        float e = ssrc + g_s2dst[snbr[t]];
        sw[t] = e > 0.f ? e : NEG_SLOPE * e;
    }
    __syncthreads();
    if (tid < 32) {
        float m = -1e30f;
        for (int j = tid; j < deg; j += 32) m = fmaxf(m, sw[j]);
        #pragma unroll
        for (int d = 16; d; d >>= 1) m = fmaxf(m, __shfl_xor_sync(0xffffffffu, m, d));
        float s = 0.f;
        for (int j = tid; j < deg; j += 32) s += __expf(sw[j] - m);
        #pragma unroll
        for (int d = 16; d; d >>= 1) s += __shfl_xor_sync(0xffffffffu, s, d);
        const float rinv = 1.f / s;
        for (int j = tid; j < deg; j += 32) sw[j] = __expf(sw[j] - m) * rinv;
    }
    __syncthreads();
    // gather fp16 Wh2 with LDG.128: 8 lanes/row, 4 rows per warp in flight
    {
        const int sub = lane >> 3;
        const int q = lane & 7;
        const int grp = wp * 4 + sub;     // 0..7
        float a0=0.f,a1=0.f,a2=0.f,a3=0.f,a4=0.f,a5=0.f,a6=0.f,a7=0.f;
        int j = grp;
        for (; j + 8 < deg; j += 16) {
            int na = snbr[j], nb = snbr[j + 8];
            float wa = sw[j], wb = sw[j + 8];
            uint4 ra = *(const uint4*)(g_Wh2h + (size_t)na * OUTD + q * 8);
            uint4 rb = *(const uint4*)(g_Wh2h + (size_t)nb * OUTD + q * 8);
            float2 p;
            p = __half22float2(*(__half2*)&ra.x); a0 = fmaf(wa, p.x, a0); a1 = fmaf(wa, p.y, a1);
            p = __half22float2(*(__half2*)&ra.y); a2 = fmaf(wa, p.x, a2); a3 = fmaf(wa, p.y, a3);
            p = __half22float2(*(__half2*)&ra.z); a4 = fmaf(wa, p.x, a4); a5 = fmaf(wa, p.y, a5);
            p = __half22float2(*(__half2*)&ra.w); a6 = fmaf(wa, p.x, a6); a7 = fmaf(wa, p.y, a7);
            p = __half22float2(*(__half2*)&rb.x); a0 = fmaf(wb, p.x, a0); a1 = fmaf(wb, p.y, a1);
            p = __half22float2(*(__half2*)&rb.y); a2 = fmaf(wb, p.x, a2); a3 = fmaf(wb, p.y, a3);
            p = __half22float2(*(__half2*)&rb.z); a4 = fmaf(wb, p.x, a4); a5 = fmaf(wb, p.y, a5);
            p = __half22float2(*(__half2*)&rb.w); a6 = fmaf(wb, p.x, a6); a7 = fmaf(wb, p.y, a7);
        }
        for (; j < deg; j += 8) {
            int na = snbr[j];
            float wa = sw[j];
            uint4 ra = *(const uint4*)(g_Wh2h + (size_t)na * OUTD + q * 8);
            float2 p;
            p = __half22float2(*(__half2*)&ra.x); a0 = fmaf(wa, p.x, a0); a1 = fmaf(wa, p.y, a1);
            p = __half22float2(*(__half2*)&ra.y); a2 = fmaf(wa, p.x, a2); a3 = fmaf(wa, p.y, a3);
            p = __half22float2(*(__half2*)&ra.z); a4 = fmaf(wa, p.x, a4); a5 = fmaf(wa, p.y, a5);
            p = __half22float2(*(__half2*)&ra.w); a6 = fmaf(wa, p.x, a6); a7 = fmaf(wa, p.y, a7);
        }
        float* dstp = &sred[grp][q * 8];
        dstp[0]=a0; dstp[1]=a1; dstp[2]=a2; dstp[3]=a3;
        dstp[4]=a4; dstp[5]=a5; dstp[6]=a6; dstp[7]=a7;
    }
    __syncthreads();
    {
        float v = sred[0][tid] + sred[1][tid] + sred[2][tid] + sred[3][tid]
                + sred[4][tid] + sred[5][tid] + sred[6][tid] + sred[7][tid];
        out[(size_t)i * OUTD + tid] = v;
    }
}

// ---------------- launcher ----------------
extern "C" void kernel_launch(void* const* d_in, const int* in_sizes, int n_in,
                              void* d_out, int out_size) {
    const float* adj = (const float*)d_in[0];
    const float* h   = (const float*)d_in[1];
    const float* W1  = (const float*)d_in[2];
    const float* a1s = (const float*)d_in[3];
    const float* a1d = (const float*)d_in[4];
    const float* W2  = (const float*)d_in[5];
    const float* a2s = (const float*)d_in[6];
    const float* a2d = (const float*)d_in[7];
    float* out = (float*)d_out;

    build_and_gemm1<<<1250, 256>>>(adj, h, W1, a1s, a1d);
    agg1_gemm2<<<NN, 128>>>(W2, a2s, a2d);
    agg2<<<NN, 64>>>(out);
}